// round 14
// baseline (speedup 1.0000x reference)
#include <cuda_runtime.h>
#include <cuda_bf16.h>
#include <math.h>
#include <stdint.h>

#define NB 2
#define MM 512
#define DD 128
#define HH 8
#define DIN 64
#define NM (NB*MM)   // 1024

typedef unsigned long long u64;

// ================= packed f32x2 helpers ===========================================
__device__ __forceinline__ u64 pk2(float lo, float hi) {
    u64 r; asm("mov.b64 %0, {%1,%2};" : "=l"(r) : "f"(lo), "f"(hi)); return r;
}
__device__ __forceinline__ void fma2(u64& d, u64 a, u64 b) {
    asm("fma.rn.f32x2 %0, %1, %2, %0;" : "+l"(d) : "l"(a), "l"(b));
}
__device__ __forceinline__ u64 add2(u64 a, u64 b) {
    u64 r; asm("add.rn.f32x2 %0, %1, %2;" : "=l"(r) : "l"(a), "l"(b)); return r;
}
__device__ __forceinline__ float2 up2(u64 v) {
    float lo, hi; asm("mov.b64 {%0,%1}, %2;" : "=f"(lo), "=f"(hi) : "l"(v));
    return make_float2(lo, hi);
}

// ================= mma.sync / cp.async helpers =====================================
__device__ __forceinline__ uint32_t smem_to_u32(const void* p) {
    uint32_t a;
    asm("{ .reg .u64 t; cvta.to.shared.u64 t, %1; cvt.u32.u64 %0, t; }" : "=r"(a) : "l"(p));
    return a;
}
__device__ __forceinline__ void ldsm4(uint32_t& r0, uint32_t& r1, uint32_t& r2,
                                      uint32_t& r3, uint32_t addr) {
    asm volatile("ldmatrix.sync.aligned.m8n8.x4.shared.b16 {%0,%1,%2,%3}, [%4];"
                 : "=r"(r0), "=r"(r1), "=r"(r2), "=r"(r3) : "r"(addr));
}
__device__ __forceinline__ void mma16816(float* d, uint32_t a0, uint32_t a1,
                                         uint32_t a2, uint32_t a3,
                                         uint32_t b0, uint32_t b1) {
    asm volatile("mma.sync.aligned.m16n8k16.row.col.f32.bf16.bf16.f32 "
                 "{%0,%1,%2,%3},{%4,%5,%6,%7},{%8,%9},{%0,%1,%2,%3};"
                 : "+f"(d[0]), "+f"(d[1]), "+f"(d[2]), "+f"(d[3])
                 : "r"(a0), "r"(a1), "r"(a2), "r"(a3), "r"(b0), "r"(b1));
}
__device__ __forceinline__ void cp16(uint32_t s, const void* g) {
    asm volatile("cp.async.cg.shared.global [%0], [%1], 16;" :: "r"(s), "l"(g));
}
#define CP_COMMIT() asm volatile("cp.async.commit_group;" ::: "memory")
#define CP_WAIT0()  asm volatile("cp.async.wait_group 0;" ::: "memory")

#define KT 32
#define SPAD 40

// C[128,128] += A[128,K] @ B[128,K]^T. 256 thr, 8 warps (2x4). cp.async 2-stage.
__device__ __forceinline__ void mma_loop(
    const __nv_bfloat16* __restrict__ A, int lda,
    const __nv_bfloat16* __restrict__ B, int ldb,
    int nkt, float acc[4][4][4])
{
    __shared__ __nv_bfloat16 As[2][128][SPAD];
    __shared__ __nv_bfloat16 Bs[2][128][SPAD];
    int tid = threadIdx.x, lane = tid & 31, wid = tid >> 5;
    int wm = wid >> 2, wn = wid & 3;

    int lrow = tid >> 1, lcol = (tid & 1) << 4;
    const __nv_bfloat16* Ag = A + (int64_t)lrow * lda + lcol;
    const __nv_bfloat16* Bg = B + (int64_t)lrow * ldb + lcol;

    uint32_t asb = smem_to_u32(As), bsb = smem_to_u32(Bs);
    int arow = ((lane >> 3) & 1) * 8 + (lane & 7);
    int acol = ((lane >> 4) & 1) * 8;
    int brow = ((lane >> 4) & 1) * 8 + (lane & 7);
    int bcol = ((lane >> 3) & 1) * 8;

    uint32_t adst = asb + (lrow * SPAD + lcol) * 2;
    uint32_t bdst = bsb + (lrow * SPAD + lcol) * 2;
    const uint32_t BUFB = 128 * SPAD * 2;

    auto issue = [&](int kt, int bf) {
        cp16(adst + bf * BUFB,      Ag + kt * KT);
        cp16(adst + bf * BUFB + 16, Ag + kt * KT + 8);
        cp16(bdst + bf * BUFB,      Bg + kt * KT);
        cp16(bdst + bf * BUFB + 16, Bg + kt * KT + 8);
        CP_COMMIT();
    };

    issue(0, 0);
    int buf = 0;
    for (int kt = 0; kt < nkt; kt++) {
        CP_WAIT0();
        __syncthreads();
        if (kt + 1 < nkt) issue(kt + 1, buf ^ 1);
        #pragma unroll
        for (int kf = 0; kf < 2; kf++) {
            uint32_t a[4][4];
            #pragma unroll
            for (int mf = 0; mf < 4; mf++)
                ldsm4(a[mf][0], a[mf][1], a[mf][2], a[mf][3],
                      asb + buf * BUFB + ((wm * 64 + mf * 16 + arow) * SPAD + kf * 16 + acol) * 2);
            uint32_t b[2][4];
            #pragma unroll
            for (int p = 0; p < 2; p++)
                ldsm4(b[p][0], b[p][1], b[p][2], b[p][3],
                      bsb + buf * BUFB + ((wn * 32 + p * 16 + brow) * SPAD + kf * 16 + bcol) * 2);
            #pragma unroll
            for (int mf = 0; mf < 4; mf++)
                #pragma unroll
                for (int nf = 0; nf < 4; nf++)
                    mma16816(acc[mf][nf], a[mf][0], a[mf][1], a[mf][2], a[mf][3],
                             b[nf >> 1][(nf & 1) * 2], b[nf >> 1][(nf & 1) * 2 + 1]);
        }
        buf ^= 1;
    }
}

// C[64,128] += A[64,K] @ B[128,K]^T. 256 thr, 8 warps (2x4). cp.async 2-stage.
__device__ __forceinline__ void mma_loop64(
    const __nv_bfloat16* __restrict__ A, int lda,
    const __nv_bfloat16* __restrict__ B, int ldb,
    int nkt, float acc[2][4][4])
{
    __shared__ __nv_bfloat16 As[2][64][SPAD];
    __shared__ __nv_bfloat16 Bs[2][128][SPAD];
    int tid = threadIdx.x, lane = tid & 31, wid = tid >> 5;
    int wm = wid >> 2, wn = wid & 3;

    int arow_l = tid >> 2, acol_l = (tid & 3) << 3;
    int lrow = tid >> 1, lcol = (tid & 1) << 4;
    const __nv_bfloat16* Ag = A + (int64_t)arow_l * lda + acol_l;
    const __nv_bfloat16* Bg = B + (int64_t)lrow * ldb + lcol;

    uint32_t asb = smem_to_u32(As), bsb = smem_to_u32(Bs);
    int arow = ((lane >> 3) & 1) * 8 + (lane & 7);
    int acol = ((lane >> 4) & 1) * 8;
    int brow = ((lane >> 4) & 1) * 8 + (lane & 7);
    int bcol = ((lane >> 3) & 1) * 8;

    uint32_t adst = asb + (arow_l * SPAD + acol_l) * 2;
    uint32_t bdst = bsb + (lrow * SPAD + lcol) * 2;
    const uint32_t ABUF = 64 * SPAD * 2;
    const uint32_t BBUF = 128 * SPAD * 2;

    auto issue = [&](int kt, int bf) {
        cp16(adst + bf * ABUF,      Ag + kt * KT);
        cp16(bdst + bf * BBUF,      Bg + kt * KT);
        cp16(bdst + bf * BBUF + 16, Bg + kt * KT + 8);
        CP_COMMIT();
    };

    issue(0, 0);
    int buf = 0;
    for (int kt = 0; kt < nkt; kt++) {
        CP_WAIT0();
        __syncthreads();
        if (kt + 1 < nkt) issue(kt + 1, buf ^ 1);
        #pragma unroll
        for (int kf = 0; kf < 2; kf++) {
            uint32_t a[2][4];
            #pragma unroll
            for (int mf = 0; mf < 2; mf++)
                ldsm4(a[mf][0], a[mf][1], a[mf][2], a[mf][3],
                      asb + buf * ABUF + ((wm * 32 + mf * 16 + arow) * SPAD + kf * 16 + acol) * 2);
            uint32_t b[2][4];
            #pragma unroll
            for (int p = 0; p < 2; p++)
                ldsm4(b[p][0], b[p][1], b[p][2], b[p][3],
                      bsb + buf * BBUF + ((wn * 32 + p * 16 + brow) * SPAD + kf * 16 + bcol) * 2);
            #pragma unroll
            for (int mf = 0; mf < 2; mf++)
                #pragma unroll
                for (int nf = 0; nf < 4; nf++)
                    mma16816(acc[mf][nf], a[mf][0], a[mf][1], a[mf][2], a[mf][3],
                             b[nf >> 1][(nf & 1) * 2], b[nf >> 1][(nf & 1) * 2 + 1]);
        }
        buf ^= 1;
    }
}

// ================= scratch =========================================================
#define OFF_TMP   0
#define OFF_H     (OFF_TMP + NM*2*DD)
#define OFF_S     (OFF_H   + NM*DD)              // K-split partials region
#define OFF_ATTC  (OFF_S   + HH*NB*MM*MM)
#define OFF_T2    (OFF_ATTC+ HH*NM*DD)
#define OFF_AB    (OFF_T2  + NM*DD)
#define OFF_HB    (OFF_AB  + 2*NM*DD)
#define OFF_WTB   (OFF_HB  + NM*DD/2)
#define OFF_KB    (OFF_WTB + 3*HH*DD*DD/2)
#define OFF_QB    (OFF_KB  + HH*NM*DD/2)
#define OFF_VTB   (OFF_QB  + HH*NM*DD/2)
#define OFF_ALB   (OFF_VTB + HH*NM*DD/2)
#define OFF_FVWT  (OFF_ALB + HH*NB*MM*MM/2)
#define SCRATCH_TOTAL (OFF_FVWT + NM*DD/8)

__device__ float g_scratch[SCRATCH_TOTAL];

#define F_TRANSB 1
#define F_RELU   2
#define F_LEAKY  4
#define F_TE     8
#define F_BIAS   16
#define F_ADD    32
#define F_AR     64

// ================= scalar FFMA2 GEMM ===============================================
template<int F>
__device__ __forceinline__ void gemm_body(
    const float* __restrict__ A, const float* __restrict__ B,
    const float* __restrict__ bias, const float* __restrict__ addsrc,
    float* __restrict__ C, int Kd, int Nc, int ldc, int ktb, int kte,
    const float* __restrict__ abias, int nra, int64_t strideAR)
{
    __shared__ float As[2][16][128];
    __shared__ float Bs[2][16][128];
    int tid = threadIdx.x;
    int tx = tid & 15, ty = tid >> 4;
    int m0 = blockIdx.y << 6, n0 = blockIdx.x << 7;

    int ar = tid >> 1, ac = (tid & 1) << 3;
    const float* Ap = A + (int64_t)(m0 + ar) * Kd + ac;
    int bk = tid >> 3, bc = (tid & 7) << 4;
    const float* Bp = (F & F_TRANSB)
        ? B + (int64_t)(n0 + tid) * Kd
        : B + (int64_t)bk * Nc + n0 + bc;

    u64 acc[8][4];
    #pragma unroll
    for (int i = 0; i < 8; i++)
        #pragma unroll
        for (int p = 0; p < 4; p++) acc[i][p] = 0ull;

    float4 la0, la1, lb[4];
    auto loadG = [&](int kt) {
        la0 = *(const float4*)(Ap + kt * 16);
        la1 = *(const float4*)(Ap + kt * 16 + 4);
        if (F & F_AR) {
            for (int r = 1; r < nra; r++) {
                float4 u0 = *(const float4*)(Ap + r * strideAR + kt * 16);
                float4 u1 = *(const float4*)(Ap + r * strideAR + kt * 16 + 4);
                la0.x += u0.x; la0.y += u0.y; la0.z += u0.z; la0.w += u0.w;
                la1.x += u1.x; la1.y += u1.y; la1.z += u1.z; la1.w += u1.w;
            }
            float4 b0 = *(const float4*)(abias + kt * 16 + ac);
            float4 b1 = *(const float4*)(abias + kt * 16 + ac + 4);
            la0.x = fmaxf(la0.x + b0.x, 0.f); la0.y = fmaxf(la0.y + b0.y, 0.f);
            la0.z = fmaxf(la0.z + b0.z, 0.f); la0.w = fmaxf(la0.w + b0.w, 0.f);
            la1.x = fmaxf(la1.x + b1.x, 0.f); la1.y = fmaxf(la1.y + b1.y, 0.f);
            la1.z = fmaxf(la1.z + b1.z, 0.f); la1.w = fmaxf(la1.w + b1.w, 0.f);
        }
        if (F & F_TE) {
            int kb = kt * 16 + ac;
            la0.x += sinf((float)(kb + 0) * (5.0f / 63.0f));
            la0.y += sinf((float)(kb + 1) * (5.0f / 63.0f));
            la0.z += sinf((float)(kb + 2) * (5.0f / 63.0f));
            la0.w += sinf((float)(kb + 3) * (5.0f / 63.0f));
            la1.x += sinf((float)(kb + 4) * (5.0f / 63.0f));
            la1.y += sinf((float)(kb + 5) * (5.0f / 63.0f));
            la1.z += sinf((float)(kb + 6) * (5.0f / 63.0f));
            la1.w += sinf((float)(kb + 7) * (5.0f / 63.0f));
        }
        if (F & F_TRANSB) {
            #pragma unroll
            for (int u = 0; u < 4; u++) lb[u] = *(const float4*)(Bp + kt * 16 + 4 * u);
        } else {
            #pragma unroll
            for (int u = 0; u < 4; u++) lb[u] = *(const float4*)(Bp + (int64_t)(kt * 16) * Nc + 4 * u);
        }
    };
    auto storeS = [&](int bf) {
        *(u64*)&As[bf][ac + 0][2 * ar] = pk2(la0.x, la0.x);
        *(u64*)&As[bf][ac + 1][2 * ar] = pk2(la0.y, la0.y);
        *(u64*)&As[bf][ac + 2][2 * ar] = pk2(la0.z, la0.z);
        *(u64*)&As[bf][ac + 3][2 * ar] = pk2(la0.w, la0.w);
        *(u64*)&As[bf][ac + 4][2 * ar] = pk2(la1.x, la1.x);
        *(u64*)&As[bf][ac + 5][2 * ar] = pk2(la1.y, la1.y);
        *(u64*)&As[bf][ac + 6][2 * ar] = pk2(la1.z, la1.z);
        *(u64*)&As[bf][ac + 7][2 * ar] = pk2(la1.w, la1.w);
        if (F & F_TRANSB) {
            #pragma unroll
            for (int u = 0; u < 4; u++) {
                Bs[bf][4 * u + 0][tid] = lb[u].x; Bs[bf][4 * u + 1][tid] = lb[u].y;
                Bs[bf][4 * u + 2][tid] = lb[u].z; Bs[bf][4 * u + 3][tid] = lb[u].w;
            }
        } else {
            #pragma unroll
            for (int u = 0; u < 4; u++) *(float4*)&Bs[bf][bk][bc + 4 * u] = lb[u];
        }
    };

    loadG(ktb); storeS(0); __syncthreads();
    int buf = 0;
    for (int kt = ktb; kt < kte; kt++) {
        bool more = (kt + 1 < kte);
        if (more) loadG(kt + 1);
        #pragma unroll
        for (int kk = 0; kk < 16; kk++) {
            ulonglong2 aL0 = *(const ulonglong2*)&As[buf][kk][(ty << 3)];
            ulonglong2 aL1 = *(const ulonglong2*)&As[buf][kk][(ty << 3) + 4];
            ulonglong2 aH0 = *(const ulonglong2*)&As[buf][kk][64 + (ty << 3)];
            ulonglong2 aH1 = *(const ulonglong2*)&As[buf][kk][64 + (ty << 3) + 4];
            ulonglong2 b0  = *(const ulonglong2*)&Bs[buf][kk][(tx << 2)];
            ulonglong2 b1  = *(const ulonglong2*)&Bs[buf][kk][64 + (tx << 2)];
            u64 ad[8] = {aL0.x, aL0.y, aL1.x, aL1.y, aH0.x, aH0.y, aH1.x, aH1.y};
            u64 bd[4] = {b0.x, b0.y, b1.x, b1.y};
            #pragma unroll
            for (int i = 0; i < 8; i++) {
                fma2(acc[i][0], ad[i], bd[0]);
                fma2(acc[i][1], ad[i], bd[1]);
                fma2(acc[i][2], ad[i], bd[2]);
                fma2(acc[i][3], ad[i], bd[3]);
            }
        }
        if (more) { storeS(buf ^ 1); __syncthreads(); buf ^= 1; }
    }

    #pragma unroll
    for (int i = 0; i < 8; i++) {
        int row = m0 + ((i < 4) ? ((ty << 2) + i) : (32 + (ty << 2) + i - 4));
        float2 q0 = up2(acc[i][0]), q1 = up2(acc[i][1]);
        float2 q2 = up2(acc[i][2]), q3 = up2(acc[i][3]);
        float o[8] = {q0.x, q0.y, q1.x, q1.y, q2.x, q2.y, q3.x, q3.y};
        #pragma unroll
        for (int j = 0; j < 8; j++) {
            int col = n0 + ((j < 4) ? ((tx << 2) + j) : (64 + (tx << 2) + j - 4));
            float v = o[j];
            if (F & F_BIAS)  v += bias[col];
            if (F & F_RELU)  v = fmaxf(v, 0.0f);
            if (F & F_LEAKY) v = (v >= 0.0f) ? v : 0.2f * v;
            if (F & F_ADD)   v += addsrc[(int64_t)row * ldc + col];
            o[j] = v;
        }
        *(float4*)&C[(int64_t)row * ldc + n0 + (tx << 2)]      = make_float4(o[0], o[1], o[2], o[3]);
        *(float4*)&C[(int64_t)row * ldc + n0 + 64 + (tx << 2)] = make_float4(o[4], o[5], o[6], o[7]);
    }
}

template<int F, int NKS>
__global__ __launch_bounds__(128, 4)
void gemm_k(const float* __restrict__ A, const float* __restrict__ B,
            const float* __restrict__ bias, const float* __restrict__ addsrc,
            float* __restrict__ C, int Kd, int Nc, int ldc,
            int64_t sA, int64_t sB, int64_t sBias,
            int zdiv, int64_t sC1, int64_t sC2, int64_t sPart,
            const float* abias, int nra, int64_t strideAR)
{
    int zz = blockIdx.z;
    int z = zz / NKS, ks = zz % NKS;
    int ktn = Kd >> 4;
    int ktb = ks * (ktn / NKS), kte = ktb + ktn / NKS;
    const float* bz = (F & F_BIAS) ? bias + sBias * z : nullptr;
    float* Cz = C + (int64_t)(z / zdiv) * sC1 + (int64_t)(z % zdiv) * sC2
                  + (int64_t)ks * sPart;
    gemm_body<F>(A + sA * z, B + sB * z, bz, addsrc, Cz, Kd, Nc, ldc, ktb, kte,
                 abias, nra, strideAR);
}

// ================= float2-granularity K-split reduce ===============================
template<int F, int NKS>
__global__ __launch_bounds__(256)
void reduce_k(const float2* __restrict__ P, const float* __restrict__ bias,
              const float2* __restrict__ addsrc, float2* __restrict__ C,
              int totalf2, int ncf2)
{
    int idx = blockIdx.x * 256 + threadIdx.x;
    if (idx >= totalf2) return;
    float2 s = P[idx];
    #pragma unroll
    for (int k = 1; k < NKS; k++) {
        float2 t = P[idx + (int64_t)k * totalf2];
        s.x += t.x; s.y += t.y;
    }
    if (F & F_BIAS) {
        float2 b = ((const float2*)bias)[idx % ncf2];
        s.x += b.x; s.y += b.y;
    }
    if (F & F_RELU) { s.x = fmaxf(s.x, 0.f); s.y = fmaxf(s.y, 0.f); }
    if (F & F_ADD)  { float2 a = addsrc[idx]; s.x += a.x; s.y += a.y; }
    C[idx] = s;
}

// ================= fused prep ======================================================
__global__ __launch_bounds__(256)
void fuse_prep_k(const float2* __restrict__ Ph, const float* __restrict__ fn_b2,
                 float2* __restrict__ h, __nv_bfloat16* __restrict__ hb,
                 const float* __restrict__ wk, const float* __restrict__ wq,
                 const float* __restrict__ wv, const float* __restrict__ fv_w1,
                 __nv_bfloat16* __restrict__ wtb, __nv_bfloat16* __restrict__ fvwt)
{
    int b = blockIdx.x, t = threadIdx.x;
    if (b < 256) {
        int idx = b * 256 + t;
        float2 s = Ph[idx];
        #pragma unroll
        for (int k = 1; k < 8; k++) {
            float2 v = Ph[idx + k * (NM * DD / 2)];
            s.x += v.x; s.y += v.y;
        }
        float2 bb = ((const float2*)fn_b2)[idx & 63];
        s.x += bb.x; s.y += bb.y;
        h[idx] = s;
        __nv_bfloat162 p = __floats2bfloat162_rn(s.x, s.y);
        *(uint32_t*)&hb[idx * 2] = *(uint32_t*)&p;
        return;
    }
    __shared__ float ts[32][33];
    int c = t & 31, r0 = t >> 5;
    if (b < 640) {
        int q = b - 256;
        int mi = q >> 4, ti = q & 15;
        int kb = ti >> 2, nb = ti & 3;
        int w = mi / 8, hd = mi & 7;
        const float* src = ((w == 0) ? wk : (w == 1) ? wq : wv) + hd * 16384;
        #pragma unroll
        for (int i = 0; i < 4; i++) {
            int r = r0 + 8 * i;
            ts[r][c] = src[(kb * 32 + r) * 128 + nb * 32 + c];
        }
        __syncthreads();
        int ck = (t & 15) << 1, rn0 = t >> 4;
        __nv_bfloat16* dst = wtb + (int64_t)mi * 16384;
        #pragma unroll
        for (int i = 0; i < 2; i++) {
            int rn = rn0 + 16 * i;
            __nv_bfloat162 p = __floats2bfloat162_rn(ts[ck][rn], ts[ck + 1][rn]);
            *(uint32_t*)&dst[(nb * 32 + rn) * 128 + kb * 32 + ck] = *(uint32_t*)&p;
        }
    } else {
        int q = b - 640;
        int kb = q >> 2, nb = q & 3;
        #pragma unroll
        for (int i = 0; i < 4; i++) {
            int r = r0 + 8 * i;
            ts[r][c] = fv_w1[(kb * 32 + r) * 128 + nb * 32 + c];
        }
        __syncthreads();
        int ck = (t & 15) << 1, rn0 = t >> 4;
        #pragma unroll
        for (int i = 0; i < 2; i++) {
            int rn = rn0 + 16 * i;
            __nv_bfloat162 p = __floats2bfloat162_rn(ts[ck][rn], ts[ck + 1][rn]);
            *(uint32_t*)&fvwt[(int64_t)(nb * 32 + rn) * 1024 + kb * 32 + ck] = *(uint32_t*)&p;
        }
    }
}

// ================= KQV via mma.sync, M-tile 64 =====================================
__global__ __launch_bounds__(256)
void kqv_mma_k(const __nv_bfloat16* __restrict__ hb, const __nv_bfloat16* __restrict__ wtb,
               const float* __restrict__ bk, const float* __restrict__ bq,
               const float* __restrict__ bv,
               __nv_bfloat16* __restrict__ Kb, __nv_bfloat16* __restrict__ Qb,
               __nv_bfloat16* __restrict__ Vtb)
{
    __shared__ __nv_bfloat16 Vs[128][72];
    int z = blockIdx.z, which = z >> 3, head = z & 7;
    int m0 = blockIdx.y << 6;
    float acc[2][4][4] = {};
    mma_loop64(hb + (int64_t)m0 * DD, DD,
               wtb + (int64_t)z * DD * DD, DD, DD / KT, acc);

    int tid = threadIdx.x;
    int lane = tid & 31, wid = tid >> 5;
    int wm = wid >> 2, wn = wid & 3;
    const float* bias = ((which == 0) ? bk : (which == 1) ? bq : bv) + head * DD;

    if (which < 2) {
        __nv_bfloat16* out = ((which == 0) ? Kb : Qb) + (int64_t)head * NM * DD;
        #pragma unroll
        for (int mf = 0; mf < 2; mf++) {
            #pragma unroll
            for (int nf = 0; nf < 4; nf++) {
                int r   = wm * 32 + mf * 16 + (lane >> 2);
                int col = wn * 32 + nf * 8 + ((lane & 3) << 1);
                float b0 = bias[col], b1 = bias[col + 1];
                __nv_bfloat162 p0 = __floats2bfloat162_rn(acc[mf][nf][0] + b0, acc[mf][nf][1] + b1);
                __nv_bfloat162 p1 = __floats2bfloat162_rn(acc[mf][nf][2] + b0, acc[mf][nf][3] + b1);
                *(uint32_t*)&out[(int64_t)(m0 + r) * DD + col]     = *(uint32_t*)&p0;
                *(uint32_t*)&out[(int64_t)(m0 + r + 8) * DD + col] = *(uint32_t*)&p1;
            }
        }
    } else {
        __syncthreads();
        #pragma unroll
        for (int mf = 0; mf < 2; mf++) {
            #pragma unroll
            for (int nf = 0; nf < 4; nf++) {
                int r   = wm * 32 + mf * 16 + (lane >> 2);
                int col = wn * 32 + nf * 8 + ((lane & 3) << 1);
                float b0 = bias[col], b1 = bias[col + 1];
                Vs[col][r]         = __float2bfloat16(acc[mf][nf][0] + b0);
                Vs[col + 1][r]     = __float2bfloat16(acc[mf][nf][1] + b1);
                Vs[col][r + 8]     = __float2bfloat16(acc[mf][nf][2] + b0);
                Vs[col + 1][r + 8] = __float2bfloat16(acc[mf][nf][3] + b1);
            }
        }
        __syncthreads();
        int d = tid >> 1, half = tid & 1;
        int n = m0 >> 9;
        __nv_bfloat16* vt = Vtb + ((int64_t)(head * 2 + n) * DD + d) * MM
                            + (m0 & 511) + half * 32;
        #pragma unroll
        for (int q = 0; q < 4; q++)
            *(uint4*)(vt + 8 * q) = *(const uint4*)&Vs[d][half * 32 + 8 * q];
    }
}

// ================= fused scores+softmax: alpha = softmax(leaky(K @ Q^T)) ===========
#define SS_SMEM (2*64*SPAD*2 + 2*512*SPAD*2)   // 92160 bytes
__global__ __launch_bounds__(256)
void scores_soft_k(const __nv_bfloat16* __restrict__ Kb,
                   const __nv_bfloat16* __restrict__ Qb,
                   __nv_bfloat16* __restrict__ ab)
{
    extern __shared__ char dsm[];
    int tid = threadIdx.x, lane = tid & 31, wid = tid >> 5;
    int z = blockIdx.z, h = z >> 1, n = z & 1;
    int m0 = blockIdx.y << 6;

    const __nv_bfloat16* Ag = Kb + ((int64_t)h * NM + n * MM + m0) * DD;
    const __nv_bfloat16* Bg = Qb + ((int64_t)h * NM + n * MM) * DD;

    uint32_t asb = smem_to_u32(dsm);
    uint32_t bsb = asb + 2 * 64 * SPAD * 2;
    const uint32_t ABUF = 64 * SPAD * 2;
    const uint32_t BBUF = 512 * SPAD * 2;

    int arow = ((lane >> 3) & 1) * 8 + (lane & 7);
    int acol = ((lane >> 4) & 1) * 8;
    int brow = ((lane >> 4) & 1) * 8 + (lane & 7);
    int bcol = ((lane >> 3) & 1) * 8;

    int ar_l = tid >> 2, ach = (tid & 3) << 3;
    auto issue = [&](int kt, int bf) {
        cp16(asb + bf * ABUF + (ar_l * SPAD + ach) * 2, Ag + (int64_t)ar_l * DD + kt * KT + ach);
        #pragma unroll
        for (int i = 0; i < 8; i++) {
            int id = tid + 256 * i;
            int br_l = id >> 2, bch = (id & 3) << 3;
            cp16(bsb + bf * BBUF + (br_l * SPAD + bch) * 2, Bg + (int64_t)br_l * DD + kt * KT + bch);
        }
        CP_COMMIT();
    };

    float acc[4][8][4];
    #pragma unroll
    for (int mf = 0; mf < 4; mf++)
        #pragma unroll
        for (int nf = 0; nf < 8; nf++)
            #pragma unroll
            for (int i = 0; i < 4; i++) acc[mf][nf][i] = 0.f;

    issue(0, 0);
    int buf = 0;
    for (int kt = 0; kt < 4; kt++) {
        CP_WAIT0();
        __syncthreads();
        if (kt + 1 < 4) issue(kt + 1, buf ^ 1);
        #pragma unroll
        for (int kf = 0; kf < 2; kf++) {
            uint32_t a[4][4];
            #pragma unroll
            for (int mf = 0; mf < 4; mf++)
                ldsm4(a[mf][0], a[mf][1], a[mf][2], a[mf][3],
                      asb + buf * ABUF + ((mf * 16 + arow) * SPAD + kf * 16 + acol) * 2);
            uint32_t b[4][4];
            #pragma unroll
            for (int p = 0; p < 4; p++)
                ldsm4(b[p][0], b[p][1], b[p][2], b[p][3],
                      bsb + buf * BBUF + ((wid * 64 + p * 16 + brow) * SPAD + kf * 16 + bcol) * 2);
            #pragma unroll
            for (int mf = 0; mf < 4; mf++)
                #pragma unroll
                for (int p = 0; p < 4; p++) {
                    mma16816(acc[mf][p * 2],     a[mf][0], a[mf][1], a[mf][2], a[mf][3],
                             b[p][0], b[p][1]);
                    mma16816(acc[mf][p * 2 + 1], a[mf][0], a[mf][1], a[mf][2], a[mf][3],
                             b[p][2], b[p][3]);
                }
        }
        buf ^= 1;
    }
    __syncthreads();

    float* pmax = (float*)dsm;
    float* psum = pmax + 512;
    int r4 = lane >> 2, q = lane & 3;

    #pragma unroll
    for (int mf = 0; mf < 4; mf++) {
        float m0v = -1e30f, m1v = -1e30f;
        #pragma unroll
        for (int nf = 0; nf < 8; nf++) {
            #pragma unroll
            for (int i = 0; i < 4; i++) {
                float v = acc[mf][nf][i];
                v = (v >= 0.f) ? v : 0.2f * v;
                acc[mf][nf][i] = v;
            }
            m0v = fmaxf(m0v, fmaxf(acc[mf][nf][0], acc[mf][nf][1]));
            m1v = fmaxf(m1v, fmaxf(acc[mf][nf][2], acc[mf][nf][3]));
        }
        m0v = fmaxf(m0v, __shfl_xor_sync(0xffffffffu, m0v, 1));
        m0v = fmaxf(m0v, __shfl_xor_sync(0xffffffffu, m0v, 2));
        m1v = fmaxf(m1v, __shfl_xor_sync(0xffffffffu, m1v, 1));
        m1v = fmaxf(m1v, __shfl_xor_sync(0xffffffffu, m1v, 2));
        if (q == 0) {
            pmax[(mf * 16 + r4) * 8 + wid]     = m0v;
            pmax[(mf * 16 + 8 + r4) * 8 + wid] = m1v;
        }
    }
    __syncthreads();
    float gmx[4][2];
    #pragma unroll
    for (int mf = 0; mf < 4; mf++) {
        float g0 = pmax[(mf * 16 + r4) * 8];
        float g1 = pmax[(mf * 16 + 8 + r4) * 8];
        #pragma unroll
        for (int w = 1; w < 8; w++) {
            g0 = fmaxf(g0, pmax[(mf * 16 + r4) * 8 + w]);
            g1 = fmaxf(g1, pmax[(mf * 16 + 8 + r4) * 8 + w]);
        }
        gmx[mf][0] = g0; gmx[mf][1] = g1;
    }
    #pragma unroll
    for (int mf = 0; mf < 4; mf++) {
        float s0 = 0.f, s1 = 0.f;
        #pragma unroll
        for (int nf = 0; nf < 8; nf++) {
            float e0 = __expf(acc[mf][nf][0] - gmx[mf][0]);
            float e1 = __expf(acc[mf][nf][1] - gmx[mf][0]);
            float e2 = __expf(acc[mf][nf][2] - gmx[mf][1]);
            float e3 = __expf(acc[mf][nf][3] - gmx[mf][1]);
            acc[mf][nf][0] = e0; acc[mf][nf][1] = e1;
            acc[mf][nf][2] = e2; acc[mf][nf][3] = e3;
            s0 += e0 + e1; s1 += e2 + e3;
        }
        s0 += __shfl_xor_sync(0xffffffffu, s0, 1);
        s0 += __shfl_xor_sync(0xffffffffu, s0, 2);
        s1 += __shfl_xor_sync(0xffffffffu, s1, 1);
        s1 += __shfl_xor_sync(0xffffffffu, s1, 2);
        if (q == 0) {
            psum[(mf * 16 + r4) * 8 + wid]     = s0;
            psum[(mf * 16 + 8 + r4) * 8 + wid] = s1;
        }
    }
    __syncthreads();
    __nv_bfloat16* out = ab + (int64_t)z * MM * MM;
    #pragma unroll
    for (int mf = 0; mf < 4; mf++) {
        float g0 = 0.f, g1 = 0.f;
        #pragma unroll
        for (int w = 0; w < 8; w++) {
            g0 += psum[(mf * 16 + r4) * 8 + w];
            g1 += psum[(mf * 16 + 8 + r4) * 8 + w];
        }
        float inv0 = 1.0f / g0, inv1 = 1.0f / g1;
        int row0 = m0 + mf * 16 + r4, row1 = row0 + 8;
        #pragma unroll
        for (int nf = 0; nf < 8; nf++) {
            int col = wid * 64 + nf * 8 + (q << 1);
            __nv_bfloat162 p0 = __floats2bfloat162_rn(acc[mf][nf][0] * inv0, acc[mf][nf][1] * inv0);
            __nv_bfloat162 p1 = __floats2bfloat162_rn(acc[mf][nf][2] * inv1, acc[mf][nf][3] * inv1);
            *(uint32_t*)&out[(int64_t)row0 * MM + col] = *(uint32_t*)&p0;
            *(uint32_t*)&out[(int64_t)row1 * MM + col] = *(uint32_t*)&p1;
        }
    }
}

// ================= attV via mma.sync, M-tile 64, fused epilogue ====================
__global__ __launch_bounds__(256)
void attv_mma_k(const __nv_bfloat16* __restrict__ ab, const __nv_bfloat16* __restrict__ Vtb,
                __nv_bfloat16* __restrict__ attc)
{
    int z = blockIdx.z, h = z >> 1, n = z & 1;
    int m0 = blockIdx.y << 6;
    float acc[2][4][4] = {};
    mma_loop64(ab  + (int64_t)z * MM * MM + (int64_t)m0 * MM, MM,
               Vtb + (int64_t)z * DD * MM, MM, MM / KT, acc);

    int lane = threadIdx.x & 31, wid = threadIdx.x >> 5;
    int wm = wid >> 2, wn = wid & 3;
    #pragma unroll
    for (int mf = 0; mf < 2; mf++) {
        #pragma unroll
        for (int nf = 0; nf < 4; nf++) {
            int r   = m0 + wm * 32 + mf * 16 + (lane >> 2);
            int col = wn * 32 + nf * 8 + ((lane & 3) << 1);
            float v0 = acc[mf][nf][0]; v0 = (v0 >= 0.f) ? v0 : 0.2f * v0;
            float v1 = acc[mf][nf][1]; v1 = (v1 >= 0.f) ? v1 : 0.2f * v1;
            float v2 = acc[mf][nf][2]; v2 = (v2 >= 0.f) ? v2 : 0.2f * v2;
            float v3 = acc[mf][nf][3]; v3 = (v3 >= 0.f) ? v3 : 0.2f * v3;
            __nv_bfloat162 p0 = __floats2bfloat162_rn(v0, v1);
            __nv_bfloat162 p1 = __floats2bfloat162_rn(v2, v3);
            __nv_bfloat16* o0 = attc + (int64_t)(n * MM + r) * (HH * DD) + h * DD + col;
            __nv_bfloat16* o1 = attc + (int64_t)(n * MM + r + 8) * (HH * DD) + h * DD + col;
            *(uint32_t*)o0 = *(uint32_t*)&p0;
            *(uint32_t*)o1 = *(uint32_t*)&p1;
        }
    }
}

// ================= f_v hidden via mma.sync, M-tile 64, K-split 8 ===================
__global__ __launch_bounds__(256)
void fv1_mma_k(const __nv_bfloat16* __restrict__ attcb, const __nv_bfloat16* __restrict__ fvwt,
               float* __restrict__ P)
{
    int ks = blockIdx.z;
    int m0 = blockIdx.y << 6;
    float acc[2][4][4] = {};
    mma_loop64(attcb + (int64_t)m0 * (HH * DD) + ks * 128, HH * DD,
               fvwt + ks * 128, HH * DD, 128 / KT, acc);

    int lane = threadIdx.x & 31, wid = threadIdx.x >> 5;
    int wm = wid >> 2, wn = wid & 3;
    float* out = P + (int64_t)ks * NM * DD;
    #pragma unroll
    for (int mf = 0; mf < 2; mf++) {
        #pragma unroll
        for (int nf = 0; nf < 4; nf++) {
            int r   = m0 + wm * 32 + mf * 16 + (lane >> 2);
            int col = wn * 32 + nf * 8 + ((lane & 3) << 1);
            *(float2*)&out[(int64_t)r * DD + col]       = make_float2(acc[mf][nf][0], acc[mf][nf][1]);
            *(float2*)&out[(int64_t)(r + 8) * DD + col] = make_float2(acc[mf][nf][2], acc[mf][nf][3]);
        }
    }
}

// ================= edge kernel: packed f32x2 + abs-trick ===========================
__global__ __launch_bounds__(256)
void edge_k(const float* __restrict__ AB, const float* __restrict__ b1,
            const float* __restrict__ w2, const float* __restrict__ b2,
            float* __restrict__ out)
{
    __shared__ float Ast[DD][68];
    __shared__ float Bst[DD][36];
    __shared__ u64 w2d[DD];
    int n  = blockIdx.z;
    int i0 = blockIdx.y << 5, j0 = blockIdx.x << 5;
    const float* Ab = AB + ((int64_t)n * MM + i0) * DD;
    const float* Bb = AB + (int64_t)NM * DD + ((int64_t)n * MM + j0) * DD;
    int t = threadIdx.x;
    if (t < DD) { float w = w2[t] * 0.5f; w2d[t] = pk2(w, w); }
    #pragma unroll
    for (int c = 0; c < 4; c++) {
        int idx = t + (c << 8);
        int r  = idx >> 5;
        int d4 = (idx & 31) << 2;
        float4 a = *(const float4*)(Ab + r * DD + d4);
        *(u64*)&Ast[d4 + 0][2 * r] = pk2(a.x, a.x);
        *(u64*)&Ast[d4 + 1][2 * r] = pk2(a.y, a.y);
        *(u64*)&Ast[d4 + 2][2 * r] = pk2(a.z, a.z);
        *(u64*)&Ast[d4 + 3][2 * r] = pk2(a.w, a.w);
        float4 bvl = *(const float4*)(Bb + r * DD + d4);
        float4 bb  = *(const float4*)(b1 + d4);
        Bst[d4 + 0][r] = bvl.x + bb.x; Bst[d4 + 1][r] = bvl.y + bb.y;
        Bst[d4 + 2][r] = bvl.z + bb.z; Bst[d4 + 3][r] = bvl.w + bb.w;
    }
    __syncthreads();
    int tx = t & 15, ty = t >> 4;
    const u64 MASK = 0x7FFFFFFF7FFFFFFFull;
    u64 acc0 = 0ull, acc1 = 0ull;
    #pragma unroll 4
    for (int d = 0; d < DD; d++) {
        u64 a0 = *(const u64*)&Ast[d][ty << 2];
        u64 a1 = *(const u64*)&Ast[d][(ty << 2) + 2];
        u64 bp = *(const u64*)&Bst[d][tx << 1];
        u64 wd = w2d[d];
        u64 s0 = add2(a0, bp);
        u64 s1 = add2(a1, bp);
        u64 t0 = s0 & MASK;
        u64 t1 = s1 & MASK;
        fma2(acc0, s0, wd); fma2(acc0, t0, wd);
        fma2(acc1, s1, wd); fma2(acc1, t1, wd);
    }
    float bb = b2[0];
    const float sc = 1.0f / (float)MM;
    int i = i0 + (ty << 1), j = j0 + (tx << 1);
    float2 q0 = up2(acc0), q1 = up2(acc1);
    float* o = out + ((int64_t)n * MM + i) * MM + j;
    *(float2*)o        = make_float2((q0.x + bb) * sc, (q0.y + bb) * sc);
    *(float2*)(o + MM) = make_float2((q1.x + bb) * sc, (q1.y + bb) * sc);
}

// ================= host launcher ===================================================
extern "C" void kernel_launch(void* const* d_in, const int* in_sizes, int n_in,
                              void* d_out, int out_size)
{
    const float* x     = (const float*)d_in[0];
    const float* fn_w1 = (const float*)d_in[1];
    const float* fn_b1 = (const float*)d_in[2];
    const float* fn_w2 = (const float*)d_in[3];
    const float* fn_b2 = (const float*)d_in[4];
    const float* wk    = (const float*)d_in[5];
    const float* bk    = (const float*)d_in[6];
    const float* wq    = (const float*)d_in[7];
    const float* bq    = (const float*)d_in[8];
    const float* wv    = (const float*)d_in[9];
    const float* bv    = (const float*)d_in[10];
    const float* fv_w1 = (const float*)d_in[11];
    const float* fv_b1 = (const float*)d_in[12];
    const float* fv_w2 = (const float*)d_in[13];
    const float* fv_b2 = (const float*)d_in[14];
    const float* fe_w1 = (const float*)d_in[15];
    const float* fe_b1 = (const float*)d_in[16];
    const float* fe_w2 = (const float*)d_in[17];
    const float* fe_b2 = (const float*)d_in[18];

    float* scratch = nullptr;
    cudaGetSymbolAddress((void**)&scratch, g_scratch);
    float* h    = scratch + OFF_H;
    float* P    = scratch + OFF_S;
    float* ABuf = scratch + OFF_AB;
    __nv_bfloat16* attcb = (__nv_bfloat16*)(scratch + OFF_ATTC);
    __nv_bfloat16* hb  = (__nv_bfloat16*)(scratch + OFF_HB);
    __nv_bfloat16* wtb = (__nv_bfloat16*)(scratch + OFF_WTB);
    __nv_bfloat16* Kb  = (__nv_bfloat16*)(scratch + OFF_KB);
    __nv_bfloat16* Qb  = (__nv_bfloat16*)(scratch + OFF_QB);
    __nv_bfloat16* Vtb = (__nv_bfloat16*)(scratch + OFF_VTB);
    __nv_bfloat16* alb = (__nv_bfloat16*)(scratch + OFF_ALB);
    __nv_bfloat16* fvwt = (__nv_bfloat16*)(scratch + OFF_FVWT);

    float* x2   = (float*)d_out;
    float* edge = (float*)d_out + NM * DD;

    cudaFuncSetAttribute(scores_soft_k,
                         cudaFuncAttributeMaxDynamicSharedMemorySize, SS_SMEM);

    dim3 gb(128);
    const int MN2 = NM * DD / 2;
    const int NC2 = DD / 2;

    // 1) f_node hidden (scalar, K-split 2) -> partials
    gemm_k<F_TE, 2><<<dim3(2, 16, 2), gb>>>(
        x, fn_w1, nullptr, nullptr, P, DIN, 2 * DD, 2 * DD, 0, 0, 0, 1, 0, 0,
        (int64_t)NM * 2 * DD, nullptr, 1, 0);
    // 2) h (scalar, K-split 8); A-loader reduces f_node1 partials
    float* Ph = P + NM * 2 * DD * 2;
    gemm_k<F_AR, 8><<<dim3(1, 16, 8), gb>>>(
        P, fn_w2, nullptr, nullptr, Ph, 2 * DD, DD, DD, 0, 0, 0, 1, 0, 0,
        (int64_t)NM * DD, fn_b1, 2, (int64_t)NM * 2 * DD);
    fuse_prep_k<<<768, 256>>>((const float2*)Ph, fn_b2, (float2*)h, hb,
                              wk, wq, wv, fv_w1, wtb, fvwt);
    // 3) K/Q/V via mma.sync, M-tile 64 (384 blocks)
    kqv_mma_k<<<dim3(1, 16, 24), 256>>>(hb, wtb, bk, bq, bv, Kb, Qb, Vtb);
    // 4) fused scores + softmax -> bf16 alpha
    scores_soft_k<<<dim3(1, 8, 16), 256, SS_SMEM>>>(Kb, Qb, alb);
    // 5) attV via mma.sync -> bf16 attc (leaky + concat in epilogue)
    attv_mma_k<<<dim3(1, 8, 16), 256>>>(alb, Vtb, attcb);
    // 6) f_v hidden via mma.sync, M-tile 64, K-split 8 (128 blocks)
    fv1_mma_k<<<dim3(1, 16, 8), 256>>>(attcb, fvwt, P);
    // 7) x2 (scalar, K-split 4); A-loader reduces fv1 partials
    float* P8 = P + 8 * NM * DD;
    gemm_k<F_AR, 4><<<dim3(1, 16, 4), gb>>>(
        P, fv_w2, nullptr, nullptr, P8, DD, DD, DD, 0, 0, 0, 1, 0, 0,
        (int64_t)NM * DD, fv_b1, 8, (int64_t)NM * DD);
    reduce_k<F_BIAS | F_ADD, 4><<<256, 256>>>(
        (const float2*)P8, fv_b2, (const float2*)h, (float2*)x2, MN2, NC2);
    // 8) A/B for edges (scalar, K-split 2 + reduce)
    float* P9 = P8 + 4 * NM * DD;
    gemm_k<0, 2><<<dim3(1, 16, 4), gb>>>(
        x2, fe_w1, nullptr, nullptr, P9, DD, DD, DD,
        0, (int64_t)DD * DD, 0, 1, (int64_t)NM * DD, 0, (int64_t)2 * NM * DD,
        nullptr, 1, 0);
    reduce_k<0, 2><<<512, 256>>>(
        (const float2*)P9, nullptr, nullptr, (float2*)ABuf, 2 * MN2, NC2);
    // 9) edge (packed f32x2)
    edge_k<<<dim3(16, 16, NB), 256>>>(ABuf, fe_b1, fe_w2, fe_b2, edge);
}

// round 15
// speedup vs baseline: 1.0494x; 1.0494x over previous
#include <cuda_runtime.h>
#include <cuda_bf16.h>
#include <math.h>
#include <stdint.h>

#define NB 2
#define MM 512
#define DD 128
#define HH 8
#define DIN 64
#define NM (NB*MM)   // 1024

typedef unsigned long long u64;

// ================= packed f32x2 helpers ===========================================
__device__ __forceinline__ u64 pk2(float lo, float hi) {
    u64 r; asm("mov.b64 %0, {%1,%2};" : "=l"(r) : "f"(lo), "f"(hi)); return r;
}
__device__ __forceinline__ void fma2(u64& d, u64 a, u64 b) {
    asm("fma.rn.f32x2 %0, %1, %2, %0;" : "+l"(d) : "l"(a), "l"(b));
}
__device__ __forceinline__ u64 add2(u64 a, u64 b) {
    u64 r; asm("add.rn.f32x2 %0, %1, %2;" : "=l"(r) : "l"(a), "l"(b)); return r;
}
__device__ __forceinline__ float2 up2(u64 v) {
    float lo, hi; asm("mov.b64 {%0,%1}, %2;" : "=f"(lo), "=f"(hi) : "l"(v));
    return make_float2(lo, hi);
}

// ================= mma.sync / cp.async helpers =====================================
__device__ __forceinline__ uint32_t smem_to_u32(const void* p) {
    uint32_t a;
    asm("{ .reg .u64 t; cvta.to.shared.u64 t, %1; cvt.u32.u64 %0, t; }" : "=r"(a) : "l"(p));
    return a;
}
__device__ __forceinline__ void ldsm4(uint32_t& r0, uint32_t& r1, uint32_t& r2,
                                      uint32_t& r3, uint32_t addr) {
    asm volatile("ldmatrix.sync.aligned.m8n8.x4.shared.b16 {%0,%1,%2,%3}, [%4];"
                 : "=r"(r0), "=r"(r1), "=r"(r2), "=r"(r3) : "r"(addr));
}
__device__ __forceinline__ void mma16816(float* d, uint32_t a0, uint32_t a1,
                                         uint32_t a2, uint32_t a3,
                                         uint32_t b0, uint32_t b1) {
    asm volatile("mma.sync.aligned.m16n8k16.row.col.f32.bf16.bf16.f32 "
                 "{%0,%1,%2,%3},{%4,%5,%6,%7},{%8,%9},{%0,%1,%2,%3};"
                 : "+f"(d[0]), "+f"(d[1]), "+f"(d[2]), "+f"(d[3])
                 : "r"(a0), "r"(a1), "r"(a2), "r"(a3), "r"(b0), "r"(b1));
}
__device__ __forceinline__ void cp16(uint32_t s, const void* g) {
    asm volatile("cp.async.cg.shared.global [%0], [%1], 16;" :: "r"(s), "l"(g));
}
#define CP_COMMIT() asm volatile("cp.async.commit_group;" ::: "memory")
#define CP_WAIT0()  asm volatile("cp.async.wait_group 0;" ::: "memory")

#define KT 32
#define SPAD 40

// C[64,128] += A[64,K] @ B[128,K]^T. 256 thr, 8 warps (2x4). cp.async 2-stage.
__device__ __forceinline__ void mma_loop64(
    const __nv_bfloat16* __restrict__ A, int lda,
    const __nv_bfloat16* __restrict__ B, int ldb,
    int nkt, float acc[2][4][4])
{
    __shared__ __nv_bfloat16 As[2][64][SPAD];
    __shared__ __nv_bfloat16 Bs[2][128][SPAD];
    int tid = threadIdx.x, lane = tid & 31, wid = tid >> 5;
    int wm = wid >> 2, wn = wid & 3;

    int arow_l = tid >> 2, acol_l = (tid & 3) << 3;
    int lrow = tid >> 1, lcol = (tid & 1) << 4;
    const __nv_bfloat16* Ag = A + (int64_t)arow_l * lda + acol_l;
    const __nv_bfloat16* Bg = B + (int64_t)lrow * ldb + lcol;

    uint32_t asb = smem_to_u32(As), bsb = smem_to_u32(Bs);
    int arow = ((lane >> 3) & 1) * 8 + (lane & 7);
    int acol = ((lane >> 4) & 1) * 8;
    int brow = ((lane >> 4) & 1) * 8 + (lane & 7);
    int bcol = ((lane >> 3) & 1) * 8;

    uint32_t adst = asb + (arow_l * SPAD + acol_l) * 2;
    uint32_t bdst = bsb + (lrow * SPAD + lcol) * 2;
    const uint32_t ABUF = 64 * SPAD * 2;
    const uint32_t BBUF = 128 * SPAD * 2;

    auto issue = [&](int kt, int bf) {
        cp16(adst + bf * ABUF,      Ag + kt * KT);
        cp16(bdst + bf * BBUF,      Bg + kt * KT);
        cp16(bdst + bf * BBUF + 16, Bg + kt * KT + 8);
        CP_COMMIT();
    };

    issue(0, 0);
    int buf = 0;
    for (int kt = 0; kt < nkt; kt++) {
        CP_WAIT0();
        __syncthreads();
        if (kt + 1 < nkt) issue(kt + 1, buf ^ 1);
        #pragma unroll
        for (int kf = 0; kf < 2; kf++) {
            uint32_t a[2][4];
            #pragma unroll
            for (int mf = 0; mf < 2; mf++)
                ldsm4(a[mf][0], a[mf][1], a[mf][2], a[mf][3],
                      asb + buf * ABUF + ((wm * 32 + mf * 16 + arow) * SPAD + kf * 16 + acol) * 2);
            uint32_t b[2][4];
            #pragma unroll
            for (int p = 0; p < 2; p++)
                ldsm4(b[p][0], b[p][1], b[p][2], b[p][3],
                      bsb + buf * BBUF + ((wn * 32 + p * 16 + brow) * SPAD + kf * 16 + bcol) * 2);
            #pragma unroll
            for (int mf = 0; mf < 2; mf++)
                #pragma unroll
                for (int nf = 0; nf < 4; nf++)
                    mma16816(acc[mf][nf], a[mf][0], a[mf][1], a[mf][2], a[mf][3],
                             b[nf >> 1][(nf & 1) * 2], b[nf >> 1][(nf & 1) * 2 + 1]);
        }
        buf ^= 1;
    }
}

// ================= scratch =========================================================
#define OFF_TMP   0
#define OFF_H     (OFF_TMP + NM*2*DD)
#define OFF_S     (OFF_H   + NM*DD)              // K-split partials region
#define OFF_ATTC  (OFF_S   + HH*NB*MM*MM)
#define OFF_T2    (OFF_ATTC+ HH*NM*DD)
#define OFF_AB    (OFF_T2  + NM*DD)
#define OFF_HB    (OFF_AB  + 2*NM*DD)
#define OFF_WTB   (OFF_HB  + NM*DD/2)
#define OFF_KB    (OFF_WTB + 3*HH*DD*DD/2)
#define OFF_QB    (OFF_KB  + HH*NM*DD/2)
#define OFF_VTB   (OFF_QB  + HH*NM*DD/2)
#define OFF_ALB   (OFF_VTB + HH*NM*DD/2)
#define OFF_FVWT  (OFF_ALB + HH*NB*MM*MM/2)
#define SCRATCH_TOTAL (OFF_FVWT + NM*DD/8)

__device__ float g_scratch[SCRATCH_TOTAL];

#define F_TRANSB 1
#define F_RELU   2
#define F_LEAKY  4
#define F_TE     8
#define F_BIAS   16
#define F_ADD    32
#define F_AR     64

// ================= scalar FFMA2 GEMM ===============================================
template<int F>
__device__ __forceinline__ void gemm_body(
    const float* __restrict__ A, const float* __restrict__ B,
    const float* __restrict__ bias, const float* __restrict__ addsrc,
    float* __restrict__ C, int Kd, int Nc, int ldc, int ktb, int kte,
    const float* __restrict__ abias, int nra, int64_t strideAR)
{
    __shared__ float As[2][16][128];
    __shared__ float Bs[2][16][128];
    int tid = threadIdx.x;
    int tx = tid & 15, ty = tid >> 4;
    int m0 = blockIdx.y << 6, n0 = blockIdx.x << 7;

    int ar = tid >> 1, ac = (tid & 1) << 3;
    const float* Ap = A + (int64_t)(m0 + ar) * Kd + ac;
    int bk = tid >> 3, bc = (tid & 7) << 4;
    const float* Bp = (F & F_TRANSB)
        ? B + (int64_t)(n0 + tid) * Kd
        : B + (int64_t)bk * Nc + n0 + bc;

    u64 acc[8][4];
    #pragma unroll
    for (int i = 0; i < 8; i++)
        #pragma unroll
        for (int p = 0; p < 4; p++) acc[i][p] = 0ull;

    float4 la0, la1, lb[4];
    auto loadG = [&](int kt) {
        la0 = *(const float4*)(Ap + kt * 16);
        la1 = *(const float4*)(Ap + kt * 16 + 4);
        if (F & F_AR) {
            for (int r = 1; r < nra; r++) {
                float4 u0 = *(const float4*)(Ap + r * strideAR + kt * 16);
                float4 u1 = *(const float4*)(Ap + r * strideAR + kt * 16 + 4);
                la0.x += u0.x; la0.y += u0.y; la0.z += u0.z; la0.w += u0.w;
                la1.x += u1.x; la1.y += u1.y; la1.z += u1.z; la1.w += u1.w;
            }
            float4 b0 = *(const float4*)(abias + kt * 16 + ac);
            float4 b1 = *(const float4*)(abias + kt * 16 + ac + 4);
            la0.x = fmaxf(la0.x + b0.x, 0.f); la0.y = fmaxf(la0.y + b0.y, 0.f);
            la0.z = fmaxf(la0.z + b0.z, 0.f); la0.w = fmaxf(la0.w + b0.w, 0.f);
            la1.x = fmaxf(la1.x + b1.x, 0.f); la1.y = fmaxf(la1.y + b1.y, 0.f);
            la1.z = fmaxf(la1.z + b1.z, 0.f); la1.w = fmaxf(la1.w + b1.w, 0.f);
        }
        if (F & F_TE) {
            int kb = kt * 16 + ac;
            la0.x += sinf((float)(kb + 0) * (5.0f / 63.0f));
            la0.y += sinf((float)(kb + 1) * (5.0f / 63.0f));
            la0.z += sinf((float)(kb + 2) * (5.0f / 63.0f));
            la0.w += sinf((float)(kb + 3) * (5.0f / 63.0f));
            la1.x += sinf((float)(kb + 4) * (5.0f / 63.0f));
            la1.y += sinf((float)(kb + 5) * (5.0f / 63.0f));
            la1.z += sinf((float)(kb + 6) * (5.0f / 63.0f));
            la1.w += sinf((float)(kb + 7) * (5.0f / 63.0f));
        }
        if (F & F_TRANSB) {
            #pragma unroll
            for (int u = 0; u < 4; u++) lb[u] = *(const float4*)(Bp + kt * 16 + 4 * u);
        } else {
            #pragma unroll
            for (int u = 0; u < 4; u++) lb[u] = *(const float4*)(Bp + (int64_t)(kt * 16) * Nc + 4 * u);
        }
    };
    auto storeS = [&](int bf) {
        *(u64*)&As[bf][ac + 0][2 * ar] = pk2(la0.x, la0.x);
        *(u64*)&As[bf][ac + 1][2 * ar] = pk2(la0.y, la0.y);
        *(u64*)&As[bf][ac + 2][2 * ar] = pk2(la0.z, la0.z);
        *(u64*)&As[bf][ac + 3][2 * ar] = pk2(la0.w, la0.w);
        *(u64*)&As[bf][ac + 4][2 * ar] = pk2(la1.x, la1.x);
        *(u64*)&As[bf][ac + 5][2 * ar] = pk2(la1.y, la1.y);
        *(u64*)&As[bf][ac + 6][2 * ar] = pk2(la1.z, la1.z);
        *(u64*)&As[bf][ac + 7][2 * ar] = pk2(la1.w, la1.w);
        if (F & F_TRANSB) {
            #pragma unroll
            for (int u = 0; u < 4; u++) {
                Bs[bf][4 * u + 0][tid] = lb[u].x; Bs[bf][4 * u + 1][tid] = lb[u].y;
                Bs[bf][4 * u + 2][tid] = lb[u].z; Bs[bf][4 * u + 3][tid] = lb[u].w;
            }
        } else {
            #pragma unroll
            for (int u = 0; u < 4; u++) *(float4*)&Bs[bf][bk][bc + 4 * u] = lb[u];
        }
    };

    loadG(ktb); storeS(0); __syncthreads();
    int buf = 0;
    for (int kt = ktb; kt < kte; kt++) {
        bool more = (kt + 1 < kte);
        if (more) loadG(kt + 1);
        #pragma unroll
        for (int kk = 0; kk < 16; kk++) {
            ulonglong2 aL0 = *(const ulonglong2*)&As[buf][kk][(ty << 3)];
            ulonglong2 aL1 = *(const ulonglong2*)&As[buf][kk][(ty << 3) + 4];
            ulonglong2 aH0 = *(const ulonglong2*)&As[buf][kk][64 + (ty << 3)];
            ulonglong2 aH1 = *(const ulonglong2*)&As[buf][kk][64 + (ty << 3) + 4];
            ulonglong2 b0  = *(const ulonglong2*)&Bs[buf][kk][(tx << 2)];
            ulonglong2 b1  = *(const ulonglong2*)&Bs[buf][kk][64 + (tx << 2)];
            u64 ad[8] = {aL0.x, aL0.y, aL1.x, aL1.y, aH0.x, aH0.y, aH1.x, aH1.y};
            u64 bd[4] = {b0.x, b0.y, b1.x, b1.y};
            #pragma unroll
            for (int i = 0; i < 8; i++) {
                fma2(acc[i][0], ad[i], bd[0]);
                fma2(acc[i][1], ad[i], bd[1]);
                fma2(acc[i][2], ad[i], bd[2]);
                fma2(acc[i][3], ad[i], bd[3]);
            }
        }
        if (more) { storeS(buf ^ 1); __syncthreads(); buf ^= 1; }
    }

    #pragma unroll
    for (int i = 0; i < 8; i++) {
        int row = m0 + ((i < 4) ? ((ty << 2) + i) : (32 + (ty << 2) + i - 4));
        float2 q0 = up2(acc[i][0]), q1 = up2(acc[i][1]);
        float2 q2 = up2(acc[i][2]), q3 = up2(acc[i][3]);
        float o[8] = {q0.x, q0.y, q1.x, q1.y, q2.x, q2.y, q3.x, q3.y};
        #pragma unroll
        for (int j = 0; j < 8; j++) {
            int col = n0 + ((j < 4) ? ((tx << 2) + j) : (64 + (tx << 2) + j - 4));
            float v = o[j];
            if (F & F_BIAS)  v += bias[col];
            if (F & F_RELU)  v = fmaxf(v, 0.0f);
            if (F & F_LEAKY) v = (v >= 0.0f) ? v : 0.2f * v;
            if (F & F_ADD)   v += addsrc[(int64_t)row * ldc + col];
            o[j] = v;
        }
        *(float4*)&C[(int64_t)row * ldc + n0 + (tx << 2)]      = make_float4(o[0], o[1], o[2], o[3]);
        *(float4*)&C[(int64_t)row * ldc + n0 + 64 + (tx << 2)] = make_float4(o[4], o[5], o[6], o[7]);
    }
}

template<int F, int NKS>
__global__ __launch_bounds__(128, 4)
void gemm_k(const float* __restrict__ A, const float* __restrict__ B,
            const float* __restrict__ bias, const float* __restrict__ addsrc,
            float* __restrict__ C, int Kd, int Nc, int ldc,
            int64_t sA, int64_t sB, int64_t sBias,
            int zdiv, int64_t sC1, int64_t sC2, int64_t sPart,
            const float* abias, int nra, int64_t strideAR)
{
    int zz = blockIdx.z;
    int z = zz / NKS, ks = zz % NKS;
    int ktn = Kd >> 4;
    int ktb = ks * (ktn / NKS), kte = ktb + ktn / NKS;
    const float* bz = (F & F_BIAS) ? bias + sBias * z : nullptr;
    float* Cz = C + (int64_t)(z / zdiv) * sC1 + (int64_t)(z % zdiv) * sC2
                  + (int64_t)ks * sPart;
    gemm_body<F>(A + sA * z, B + sB * z, bz, addsrc, Cz, Kd, Nc, ldc, ktb, kte,
                 abias, nra, strideAR);
}

// ================= float2-granularity K-split reduce ===============================
template<int F, int NKS>
__global__ __launch_bounds__(256)
void reduce_k(const float2* __restrict__ P, const float* __restrict__ bias,
              const float2* __restrict__ addsrc, float2* __restrict__ C,
              int totalf2, int ncf2)
{
    int idx = blockIdx.x * 256 + threadIdx.x;
    if (idx >= totalf2) return;
    float2 s = P[idx];
    #pragma unroll
    for (int k = 1; k < NKS; k++) {
        float2 t = P[idx + (int64_t)k * totalf2];
        s.x += t.x; s.y += t.y;
    }
    if (F & F_BIAS) {
        float2 b = ((const float2*)bias)[idx % ncf2];
        s.x += b.x; s.y += b.y;
    }
    if (F & F_RELU) { s.x = fmaxf(s.x, 0.f); s.y = fmaxf(s.y, 0.f); }
    if (F & F_ADD)  { float2 a = addsrc[idx]; s.x += a.x; s.y += a.y; }
    C[idx] = s;
}

// ================= fused prep ======================================================
__global__ __launch_bounds__(256)
void fuse_prep_k(const float2* __restrict__ Ph, const float* __restrict__ fn_b2,
                 float2* __restrict__ h, __nv_bfloat16* __restrict__ hb,
                 const float* __restrict__ wk, const float* __restrict__ wq,
                 const float* __restrict__ wv, const float* __restrict__ fv_w1,
                 __nv_bfloat16* __restrict__ wtb, __nv_bfloat16* __restrict__ fvwt)
{
    int b = blockIdx.x, t = threadIdx.x;
    if (b < 256) {
        int idx = b * 256 + t;
        float2 s = Ph[idx];
        #pragma unroll
        for (int k = 1; k < 8; k++) {
            float2 v = Ph[idx + k * (NM * DD / 2)];
            s.x += v.x; s.y += v.y;
        }
        float2 bb = ((const float2*)fn_b2)[idx & 63];
        s.x += bb.x; s.y += bb.y;
        h[idx] = s;
        __nv_bfloat162 p = __floats2bfloat162_rn(s.x, s.y);
        *(uint32_t*)&hb[idx * 2] = *(uint32_t*)&p;
        return;
    }
    __shared__ float ts[32][33];
    int c = t & 31, r0 = t >> 5;
    if (b < 640) {
        int q = b - 256;
        int mi = q >> 4, ti = q & 15;
        int kb = ti >> 2, nb = ti & 3;
        int w = mi / 8, hd = mi & 7;
        const float* src = ((w == 0) ? wk : (w == 1) ? wq : wv) + hd * 16384;
        #pragma unroll
        for (int i = 0; i < 4; i++) {
            int r = r0 + 8 * i;
            ts[r][c] = src[(kb * 32 + r) * 128 + nb * 32 + c];
        }
        __syncthreads();
        int ck = (t & 15) << 1, rn0 = t >> 4;
        __nv_bfloat16* dst = wtb + (int64_t)mi * 16384;
        #pragma unroll
        for (int i = 0; i < 2; i++) {
            int rn = rn0 + 16 * i;
            __nv_bfloat162 p = __floats2bfloat162_rn(ts[ck][rn], ts[ck + 1][rn]);
            *(uint32_t*)&dst[(nb * 32 + rn) * 128 + kb * 32 + ck] = *(uint32_t*)&p;
        }
    } else {
        int q = b - 640;
        int kb = q >> 2, nb = q & 3;
        #pragma unroll
        for (int i = 0; i < 4; i++) {
            int r = r0 + 8 * i;
            ts[r][c] = fv_w1[(kb * 32 + r) * 128 + nb * 32 + c];
        }
        __syncthreads();
        int ck = (t & 15) << 1, rn0 = t >> 4;
        #pragma unroll
        for (int i = 0; i < 2; i++) {
            int rn = rn0 + 16 * i;
            __nv_bfloat162 p = __floats2bfloat162_rn(ts[ck][rn], ts[ck + 1][rn]);
            *(uint32_t*)&fvwt[(int64_t)(nb * 32 + rn) * 1024 + kb * 32 + ck] = *(uint32_t*)&p;
        }
    }
}

// ================= KQV via mma.sync, M-tile 64 =====================================
__global__ __launch_bounds__(256)
void kqv_mma_k(const __nv_bfloat16* __restrict__ hb, const __nv_bfloat16* __restrict__ wtb,
               const float* __restrict__ bk, const float* __restrict__ bq,
               const float* __restrict__ bv,
               __nv_bfloat16* __restrict__ Kb, __nv_bfloat16* __restrict__ Qb,
               __nv_bfloat16* __restrict__ Vtb)
{
    __shared__ __nv_bfloat16 Vs[128][72];
    int z = blockIdx.z, which = z >> 3, head = z & 7;
    int m0 = blockIdx.y << 6;
    float acc[2][4][4] = {};
    mma_loop64(hb + (int64_t)m0 * DD, DD,
               wtb + (int64_t)z * DD * DD, DD, DD / KT, acc);

    int tid = threadIdx.x;
    int lane = tid & 31, wid = tid >> 5;
    int wm = wid >> 2, wn = wid & 3;
    const float* bias = ((which == 0) ? bk : (which == 1) ? bq : bv) + head * DD;

    if (which < 2) {
        __nv_bfloat16* out = ((which == 0) ? Kb : Qb) + (int64_t)head * NM * DD;
        #pragma unroll
        for (int mf = 0; mf < 2; mf++) {
            #pragma unroll
            for (int nf = 0; nf < 4; nf++) {
                int r   = wm * 32 + mf * 16 + (lane >> 2);
                int col = wn * 32 + nf * 8 + ((lane & 3) << 1);
                float b0 = bias[col], b1 = bias[col + 1];
                __nv_bfloat162 p0 = __floats2bfloat162_rn(acc[mf][nf][0] + b0, acc[mf][nf][1] + b1);
                __nv_bfloat162 p1 = __floats2bfloat162_rn(acc[mf][nf][2] + b0, acc[mf][nf][3] + b1);
                *(uint32_t*)&out[(int64_t)(m0 + r) * DD + col]     = *(uint32_t*)&p0;
                *(uint32_t*)&out[(int64_t)(m0 + r + 8) * DD + col] = *(uint32_t*)&p1;
            }
        }
    } else {
        __syncthreads();
        #pragma unroll
        for (int mf = 0; mf < 2; mf++) {
            #pragma unroll
            for (int nf = 0; nf < 4; nf++) {
                int r   = wm * 32 + mf * 16 + (lane >> 2);
                int col = wn * 32 + nf * 8 + ((lane & 3) << 1);
                float b0 = bias[col], b1 = bias[col + 1];
                Vs[col][r]         = __float2bfloat16(acc[mf][nf][0] + b0);
                Vs[col + 1][r]     = __float2bfloat16(acc[mf][nf][1] + b1);
                Vs[col][r + 8]     = __float2bfloat16(acc[mf][nf][2] + b0);
                Vs[col + 1][r + 8] = __float2bfloat16(acc[mf][nf][3] + b1);
            }
        }
        __syncthreads();
        int d = tid >> 1, half = tid & 1;
        int n = m0 >> 9;
        __nv_bfloat16* vt = Vtb + ((int64_t)(head * 2 + n) * DD + d) * MM
                            + (m0 & 511) + half * 32;
        #pragma unroll
        for (int q = 0; q < 4; q++)
            *(uint4*)(vt + 8 * q) = *(const uint4*)&Vs[d][half * 32 + 8 * q];
    }
}

// ================= fused scores+softmax ============================================
#define SS_SMEM (2*64*SPAD*2 + 2*512*SPAD*2)   // 92160 bytes
__global__ __launch_bounds__(256)
void scores_soft_k(const __nv_bfloat16* __restrict__ Kb,
                   const __nv_bfloat16* __restrict__ Qb,
                   __nv_bfloat16* __restrict__ ab)
{
    extern __shared__ char dsm[];
    int tid = threadIdx.x, lane = tid & 31, wid = tid >> 5;
    int z = blockIdx.z, h = z >> 1, n = z & 1;
    int m0 = blockIdx.y << 6;

    const __nv_bfloat16* Ag = Kb + ((int64_t)h * NM + n * MM + m0) * DD;
    const __nv_bfloat16* Bg = Qb + ((int64_t)h * NM + n * MM) * DD;

    uint32_t asb = smem_to_u32(dsm);
    uint32_t bsb = asb + 2 * 64 * SPAD * 2;
    const uint32_t ABUF = 64 * SPAD * 2;
    const uint32_t BBUF = 512 * SPAD * 2;

    int arow = ((lane >> 3) & 1) * 8 + (lane & 7);
    int acol = ((lane >> 4) & 1) * 8;
    int brow = ((lane >> 4) & 1) * 8 + (lane & 7);
    int bcol = ((lane >> 3) & 1) * 8;

    int ar_l = tid >> 2, ach = (tid & 3) << 3;
    auto issue = [&](int kt, int bf) {
        cp16(asb + bf * ABUF + (ar_l * SPAD + ach) * 2, Ag + (int64_t)ar_l * DD + kt * KT + ach);
        #pragma unroll
        for (int i = 0; i < 8; i++) {
            int id = tid + 256 * i;
            int br_l = id >> 2, bch = (id & 3) << 3;
            cp16(bsb + bf * BBUF + (br_l * SPAD + bch) * 2, Bg + (int64_t)br_l * DD + kt * KT + bch);
        }
        CP_COMMIT();
    };

    float acc[4][8][4];
    #pragma unroll
    for (int mf = 0; mf < 4; mf++)
        #pragma unroll
        for (int nf = 0; nf < 8; nf++)
            #pragma unroll
            for (int i = 0; i < 4; i++) acc[mf][nf][i] = 0.f;

    issue(0, 0);
    int buf = 0;
    for (int kt = 0; kt < 4; kt++) {
        CP_WAIT0();
        __syncthreads();
        if (kt + 1 < 4) issue(kt + 1, buf ^ 1);
        #pragma unroll
        for (int kf = 0; kf < 2; kf++) {
            uint32_t a[4][4];
            #pragma unroll
            for (int mf = 0; mf < 4; mf++)
                ldsm4(a[mf][0], a[mf][1], a[mf][2], a[mf][3],
                      asb + buf * ABUF + ((mf * 16 + arow) * SPAD + kf * 16 + acol) * 2);
            uint32_t b[4][4];
            #pragma unroll
            for (int p = 0; p < 4; p++)
                ldsm4(b[p][0], b[p][1], b[p][2], b[p][3],
                      bsb + buf * BBUF + ((wid * 64 + p * 16 + brow) * SPAD + kf * 16 + bcol) * 2);
            #pragma unroll
            for (int mf = 0; mf < 4; mf++)
                #pragma unroll
                for (int p = 0; p < 4; p++) {
                    mma16816(acc[mf][p * 2],     a[mf][0], a[mf][1], a[mf][2], a[mf][3],
                             b[p][0], b[p][1]);
                    mma16816(acc[mf][p * 2 + 1], a[mf][0], a[mf][1], a[mf][2], a[mf][3],
                             b[p][2], b[p][3]);
                }
        }
        buf ^= 1;
    }
    __syncthreads();

    float* pmax = (float*)dsm;
    float* psum = pmax + 512;
    int r4 = lane >> 2, q = lane & 3;

    #pragma unroll
    for (int mf = 0; mf < 4; mf++) {
        float m0v = -1e30f, m1v = -1e30f;
        #pragma unroll
        for (int nf = 0; nf < 8; nf++) {
            #pragma unroll
            for (int i = 0; i < 4; i++) {
                float v = acc[mf][nf][i];
                v = (v >= 0.f) ? v : 0.2f * v;
                acc[mf][nf][i] = v;
            }
            m0v = fmaxf(m0v, fmaxf(acc[mf][nf][0], acc[mf][nf][1]));
            m1v = fmaxf(m1v, fmaxf(acc[mf][nf][2], acc[mf][nf][3]));
        }
        m0v = fmaxf(m0v, __shfl_xor_sync(0xffffffffu, m0v, 1));
        m0v = fmaxf(m0v, __shfl_xor_sync(0xffffffffu, m0v, 2));
        m1v = fmaxf(m1v, __shfl_xor_sync(0xffffffffu, m1v, 1));
        m1v = fmaxf(m1v, __shfl_xor_sync(0xffffffffu, m1v, 2));
        if (q == 0) {
            pmax[(mf * 16 + r4) * 8 + wid]     = m0v;
            pmax[(mf * 16 + 8 + r4) * 8 + wid] = m1v;
        }
    }
    __syncthreads();
    float gmx[4][2];
    #pragma unroll
    for (int mf = 0; mf < 4; mf++) {
        float g0 = pmax[(mf * 16 + r4) * 8];
        float g1 = pmax[(mf * 16 + 8 + r4) * 8];
        #pragma unroll
        for (int w = 1; w < 8; w++) {
            g0 = fmaxf(g0, pmax[(mf * 16 + r4) * 8 + w]);
            g1 = fmaxf(g1, pmax[(mf * 16 + 8 + r4) * 8 + w]);
        }
        gmx[mf][0] = g0; gmx[mf][1] = g1;
    }
    #pragma unroll
    for (int mf = 0; mf < 4; mf++) {
        float s0 = 0.f, s1 = 0.f;
        #pragma unroll
        for (int nf = 0; nf < 8; nf++) {
            float e0 = __expf(acc[mf][nf][0] - gmx[mf][0]);
            float e1 = __expf(acc[mf][nf][1] - gmx[mf][0]);
            float e2 = __expf(acc[mf][nf][2] - gmx[mf][1]);
            float e3 = __expf(acc[mf][nf][3] - gmx[mf][1]);
            acc[mf][nf][0] = e0; acc[mf][nf][1] = e1;
            acc[mf][nf][2] = e2; acc[mf][nf][3] = e3;
            s0 += e0 + e1; s1 += e2 + e3;
        }
        s0 += __shfl_xor_sync(0xffffffffu, s0, 1);
        s0 += __shfl_xor_sync(0xffffffffu, s0, 2);
        s1 += __shfl_xor_sync(0xffffffffu, s1, 1);
        s1 += __shfl_xor_sync(0xffffffffu, s1, 2);
        if (q == 0) {
            psum[(mf * 16 + r4) * 8 + wid]     = s0;
            psum[(mf * 16 + 8 + r4) * 8 + wid] = s1;
        }
    }
    __syncthreads();
    __nv_bfloat16* out = ab + (int64_t)z * MM * MM;
    #pragma unroll
    for (int mf = 0; mf < 4; mf++) {
        float g0 = 0.f, g1 = 0.f;
        #pragma unroll
        for (int w = 0; w < 8; w++) {
            g0 += psum[(mf * 16 + r4) * 8 + w];
            g1 += psum[(mf * 16 + 8 + r4) * 8 + w];
        }
        float inv0 = 1.0f / g0, inv1 = 1.0f / g1;
        int row0 = m0 + mf * 16 + r4, row1 = row0 + 8;
        #pragma unroll
        for (int nf = 0; nf < 8; nf++) {
            int col = wid * 64 + nf * 8 + (q << 1);
            __nv_bfloat162 p0 = __floats2bfloat162_rn(acc[mf][nf][0] * inv0, acc[mf][nf][1] * inv0);
            __nv_bfloat162 p1 = __floats2bfloat162_rn(acc[mf][nf][2] * inv1, acc[mf][nf][3] * inv1);
            *(uint32_t*)&out[(int64_t)row0 * MM + col] = *(uint32_t*)&p0;
            *(uint32_t*)&out[(int64_t)row1 * MM + col] = *(uint32_t*)&p1;
        }
    }
}

// ================= fused attV + fv1: P[h] = leaky(alpha@V) @ fvwt_h^T ==============
// stage1: att[64][128] via alpha(64x512) @ Vtb rows; stage2: att @ fvwt[:, h*128..]
// dynamic smem: stage1 A(10240)+B(20480)=30720; stage2 Att(17408)+B2(20480)=37888
#define AF_SMEM 37888
#define ATTP 136
__global__ __launch_bounds__(256)
void attv_fv1_k(const __nv_bfloat16* __restrict__ ab, const __nv_bfloat16* __restrict__ Vtb,
                const __nv_bfloat16* __restrict__ fvwt, float* __restrict__ P)
{
    extern __shared__ char dsm[];
    int tid = threadIdx.x, lane = tid & 31, wid = tid >> 5;
    int wm = wid >> 2, wn = wid & 3;
    int z = blockIdx.z, h = z >> 1, n = z & 1;
    int m0 = blockIdx.y << 6;

    uint32_t base = smem_to_u32(dsm);
    int arow = ((lane >> 3) & 1) * 8 + (lane & 7);
    int acol = ((lane >> 4) & 1) * 8;
    int brow = ((lane >> 4) & 1) * 8 + (lane & 7);
    int bcol = ((lane >> 3) & 1) * 8;

    // ---------- stage 1: att = alpha @ V^T ----------
    {
        uint32_t asb = base, bsb = base + 10240;
        const uint32_t ABUF = 64 * SPAD * 2, BBUF = 128 * SPAD * 2;
        int arow_l = tid >> 2, acol_l = (tid & 3) << 3;
        int lrow = tid >> 1, lcol = (tid & 1) << 4;
        const __nv_bfloat16* Ag = ab + (int64_t)z * MM * MM + (int64_t)(m0 + arow_l) * MM + acol_l;
        const __nv_bfloat16* Bg = Vtb + (int64_t)z * DD * MM + (int64_t)lrow * MM + lcol;
        uint32_t adst = asb + (arow_l * SPAD + acol_l) * 2;
        uint32_t bdst = bsb + (lrow * SPAD + lcol) * 2;

        auto issue = [&](int kt, int bf) {
            cp16(adst + bf * ABUF,      Ag + kt * KT);
            cp16(bdst + bf * BBUF,      Bg + kt * KT);
            cp16(bdst + bf * BBUF + 16, Bg + kt * KT + 8);
            CP_COMMIT();
        };

        float acc[2][4][4] = {};
        issue(0, 0);
        int buf = 0;
        for (int kt = 0; kt < MM / KT; kt++) {
            CP_WAIT0();
            __syncthreads();
            if (kt + 1 < MM / KT) issue(kt + 1, buf ^ 1);
            #pragma unroll
            for (int kf = 0; kf < 2; kf++) {
                uint32_t a[2][4];
                #pragma unroll
                for (int mf = 0; mf < 2; mf++)
                    ldsm4(a[mf][0], a[mf][1], a[mf][2], a[mf][3],
                          asb + buf * ABUF + ((wm * 32 + mf * 16 + arow) * SPAD + kf * 16 + acol) * 2);
                uint32_t b[2][4];
                #pragma unroll
                for (int p = 0; p < 2; p++)
                    ldsm4(b[p][0], b[p][1], b[p][2], b[p][3],
                          bsb + buf * BBUF + ((wn * 32 + p * 16 + brow) * SPAD + kf * 16 + bcol) * 2);
                #pragma unroll
                for (int mf = 0; mf < 2; mf++)
                    #pragma unroll
                    for (int nf = 0; nf < 4; nf++)
                        mma16816(acc[mf][nf], a[mf][0], a[mf][1], a[mf][2], a[mf][3],
                                 b[nf >> 1][(nf & 1) * 2], b[nf >> 1][(nf & 1) * 2 + 1]);
            }
            buf ^= 1;
        }
        __syncthreads();   // stage1 smem reads done; Att/B2 regions now writable

        // leaky + bf16 into Att[64][ATTP]
        __nv_bfloat16* Att = (__nv_bfloat16*)dsm;
        #pragma unroll
        for (int mf = 0; mf < 2; mf++) {
            #pragma unroll
            for (int nf = 0; nf < 4; nf++) {
                int r   = wm * 32 + mf * 16 + (lane >> 2);
                int col = wn * 32 + nf * 8 + ((lane & 3) << 1);
                float v0 = acc[mf][nf][0]; v0 = (v0 >= 0.f) ? v0 : 0.2f * v0;
                float v1 = acc[mf][nf][1]; v1 = (v1 >= 0.f) ? v1 : 0.2f * v1;
                float v2 = acc[mf][nf][2]; v2 = (v2 >= 0.f) ? v2 : 0.2f * v2;
                float v3 = acc[mf][nf][3]; v3 = (v3 >= 0.f) ? v3 : 0.2f * v3;
                __nv_bfloat162 p0 = __floats2bfloat162_rn(v0, v1);
                __nv_bfloat162 p1 = __floats2bfloat162_rn(v2, v3);
                *(uint32_t*)&Att[r * ATTP + col]       = *(uint32_t*)&p0;
                *(uint32_t*)&Att[(r + 8) * ATTP + col] = *(uint32_t*)&p1;
            }
        }
    }

    // ---------- stage 2: P[h] rows = Att @ fvwt[:, h*128..]^T ----------
    {
        uint32_t atb = base;                    // Att[64][ATTP]
        uint32_t b2b = base + 64 * ATTP * 2;    // 17408
        const uint32_t BBUF2 = 128 * SPAD * 2;
        int lrow = tid >> 1, lcol = (tid & 1) << 4;
        const __nv_bfloat16* Bg = fvwt + (int64_t)lrow * (HH * DD) + h * DD + lcol;
        uint32_t bdst = b2b + (lrow * SPAD + lcol) * 2;

        auto issue2 = [&](int kt, int bf) {
            cp16(bdst + bf * BBUF2,      Bg + kt * KT);
            cp16(bdst + bf * BBUF2 + 16, Bg + kt * KT + 8);
            CP_COMMIT();
        };

        float acc2[2][4][4] = {};
        issue2(0, 0);
        int buf = 0;
        for (int kt = 0; kt < 4; kt++) {
            CP_WAIT0();
            __syncthreads();   // kt=0: also makes Att visible
            if (kt + 1 < 4) issue2(kt + 1, buf ^ 1);
            #pragma unroll
            for (int kf = 0; kf < 2; kf++) {
                uint32_t a[2][4];
                #pragma unroll
                for (int mf = 0; mf < 2; mf++)
                    ldsm4(a[mf][0], a[mf][1], a[mf][2], a[mf][3],
                          atb + ((wm * 32 + mf * 16 + arow) * ATTP + kt * KT + kf * 16 + acol) * 2);
                uint32_t b[2][4];
                #pragma unroll
                for (int p = 0; p < 2; p++)
                    ldsm4(b[p][0], b[p][1], b[p][2], b[p][3],
                          b2b + buf * BBUF2 + ((wn * 32 + p * 16 + brow) * SPAD + kf * 16 + bcol) * 2);
                #pragma unroll
                for (int mf = 0; mf < 2; mf++)
                    #pragma unroll
                    for (int nf = 0; nf < 4; nf++)
                        mma16816(acc2[mf][nf], a[mf][0], a[mf][1], a[mf][2], a[mf][3],
                                 b[nf >> 1][(nf & 1) * 2], b[nf >> 1][(nf & 1) * 2 + 1]);
            }
            buf ^= 1;
        }

        float* out = P + (int64_t)h * NM * DD;
        #pragma unroll
        for (int mf = 0; mf < 2; mf++) {
            #pragma unroll
            for (int nf = 0; nf < 4; nf++) {
                int r   = n * MM + m0 + wm * 32 + mf * 16 + (lane >> 2);
                int col = wn * 32 + nf * 8 + ((lane & 3) << 1);
                *(float2*)&out[(int64_t)r * DD + col]       = make_float2(acc2[mf][nf][0], acc2[mf][nf][1]);
                *(float2*)&out[(int64_t)(r + 8) * DD + col] = make_float2(acc2[mf][nf][2], acc2[mf][nf][3]);
            }
        }
    }
}

// ================= edge kernel: packed f32x2 + abs-trick ===========================
__global__ __launch_bounds__(256)
void edge_k(const float* __restrict__ AB, const float* __restrict__ b1,
            const float* __restrict__ w2, const float* __restrict__ b2,
            float* __restrict__ out)
{
    __shared__ float Ast[DD][68];
    __shared__ float Bst[DD][36];
    __shared__ u64 w2d[DD];
    int n  = blockIdx.z;
    int i0 = blockIdx.y << 5, j0 = blockIdx.x << 5;
    const float* Ab = AB + ((int64_t)n * MM + i0) * DD;
    const float* Bb = AB + (int64_t)NM * DD + ((int64_t)n * MM + j0) * DD;
    int t = threadIdx.x;
    if (t < DD) { float w = w2[t] * 0.5f; w2d[t] = pk2(w, w); }
    #pragma unroll
    for (int c = 0; c < 4; c++) {
        int idx = t + (c << 8);
        int r  = idx >> 5;
        int d4 = (idx & 31) << 2;
        float4 a = *(const float4*)(Ab + r * DD + d4);
        *(u64*)&Ast[d4 + 0][2 * r] = pk2(a.x, a.x);
        *(u64*)&Ast[d4 + 1][2 * r] = pk2(a.y, a.y);
        *(u64*)&Ast[d4 + 2][2 * r] = pk2(a.z, a.z);
        *(u64*)&Ast[d4 + 3][2 * r] = pk2(a.w, a.w);
        float4 bvl = *(const float4*)(Bb + r * DD + d4);
        float4 bb  = *(const float4*)(b1 + d4);
        Bst[d4 + 0][r] = bvl.x + bb.x; Bst[d4 + 1][r] = bvl.y + bb.y;
        Bst[d4 + 2][r] = bvl.z + bb.z; Bst[d4 + 3][r] = bvl.w + bb.w;
    }
    __syncthreads();
    int tx = t & 15, ty = t >> 4;
    const u64 MASK = 0x7FFFFFFF7FFFFFFFull;
    u64 acc0 = 0ull, acc1 = 0ull;
    #pragma unroll 4
    for (int d = 0; d < DD; d++) {
        u64 a0 = *(const u64*)&Ast[d][ty << 2];
        u64 a1 = *(const u64*)&Ast[d][(ty << 2) + 2];
        u64 bp = *(const u64*)&Bst[d][tx << 1];
        u64 wd = w2d[d];
        u64 s0 = add2(a0, bp);
        u64 s1 = add2(a1, bp);
        u64 t0 = s0 & MASK;
        u64 t1 = s1 & MASK;
        fma2(acc0, s0, wd); fma2(acc0, t0, wd);
        fma2(acc1, s1, wd); fma2(acc1, t1, wd);
    }
    float bb = b2[0];
    const float sc = 1.0f / (float)MM;
    int i = i0 + (ty << 1), j = j0 + (tx << 1);
    float2 q0 = up2(acc0), q1 = up2(acc1);
    float* o = out + ((int64_t)n * MM + i) * MM + j;
    *(float2*)o        = make_float2((q0.x + bb) * sc, (q0.y + bb) * sc);
    *(float2*)(o + MM) = make_float2((q1.x + bb) * sc, (q1.y + bb) * sc);
}

// ================= host launcher ===================================================
extern "C" void kernel_launch(void* const* d_in, const int* in_sizes, int n_in,
                              void* d_out, int out_size)
{
    const float* x     = (const float*)d_in[0];
    const float* fn_w1 = (const float*)d_in[1];
    const float* fn_b1 = (const float*)d_in[2];
    const float* fn_w2 = (const float*)d_in[3];
    const float* fn_b2 = (const float*)d_in[4];
    const float* wk    = (const float*)d_in[5];
    const float* bk    = (const float*)d_in[6];
    const float* wq    = (const float*)d_in[7];
    const float* bq    = (const float*)d_in[8];
    const float* wv    = (const float*)d_in[9];
    const float* bv    = (const float*)d_in[10];
    const float* fv_w1 = (const float*)d_in[11];
    const float* fv_b1 = (const float*)d_in[12];
    const float* fv_w2 = (const float*)d_in[13];
    const float* fv_b2 = (const float*)d_in[14];
    const float* fe_w1 = (const float*)d_in[15];
    const float* fe_b1 = (const float*)d_in[16];
    const float* fe_w2 = (const float*)d_in[17];
    const float* fe_b2 = (const float*)d_in[18];

    float* scratch = nullptr;
    cudaGetSymbolAddress((void**)&scratch, g_scratch);
    float* h    = scratch + OFF_H;
    float* P    = scratch + OFF_S;
    float* ABuf = scratch + OFF_AB;
    __nv_bfloat16* hb  = (__nv_bfloat16*)(scratch + OFF_HB);
    __nv_bfloat16* wtb = (__nv_bfloat16*)(scratch + OFF_WTB);
    __nv_bfloat16* Kb  = (__nv_bfloat16*)(scratch + OFF_KB);
    __nv_bfloat16* Qb  = (__nv_bfloat16*)(scratch + OFF_QB);
    __nv_bfloat16* Vtb = (__nv_bfloat16*)(scratch + OFF_VTB);
    __nv_bfloat16* alb = (__nv_bfloat16*)(scratch + OFF_ALB);
    __nv_bfloat16* fvwt = (__nv_bfloat16*)(scratch + OFF_FVWT);

    float* x2   = (float*)d_out;
    float* edge = (float*)d_out + NM * DD;

    cudaFuncSetAttribute(scores_soft_k,
                         cudaFuncAttributeMaxDynamicSharedMemorySize, SS_SMEM);

    dim3 gb(128);
    const int MN2 = NM * DD / 2;
    const int NC2 = DD / 2;

    // 1) f_node hidden (scalar, K-split 2) -> partials
    gemm_k<F_TE, 2><<<dim3(2, 16, 2), gb>>>(
        x, fn_w1, nullptr, nullptr, P, DIN, 2 * DD, 2 * DD, 0, 0, 0, 1, 0, 0,
        (int64_t)NM * 2 * DD, nullptr, 1, 0);
    // 2) h (scalar, K-split 8); A-loader reduces f_node1 partials
    float* Ph = P + NM * 2 * DD * 2;
    gemm_k<F_AR, 8><<<dim3(1, 16, 8), gb>>>(
        P, fn_w2, nullptr, nullptr, Ph, 2 * DD, DD, DD, 0, 0, 0, 1, 0, 0,
        (int64_t)NM * DD, fn_b1, 2, (int64_t)NM * 2 * DD);
    fuse_prep_k<<<768, 256>>>((const float2*)Ph, fn_b2, (float2*)h, hb,
                              wk, wq, wv, fv_w1, wtb, fvwt);
    // 3) K/Q/V via mma.sync, M-tile 64
    kqv_mma_k<<<dim3(1, 16, 24), 256>>>(hb, wtb, bk, bq, bv, Kb, Qb, Vtb);
    // 4) fused scores + softmax -> bf16 alpha
    scores_soft_k<<<dim3(1, 8, 16), 256, SS_SMEM>>>(Kb, Qb, alb);
    // 5) fused attV + fv1 -> partials P[h] (no attc buffer, no fv1 kernel)
    attv_fv1_k<<<dim3(1, 8, 16), 256, AF_SMEM>>>(alb, Vtb, fvwt, P);
    // 6) x2 (scalar, K-split 4); A-loader reduces fv1 partials (sum8+fv_b1+relu)
    float* P8 = P + 8 * NM * DD;
    gemm_k<F_AR, 4><<<dim3(1, 16, 4), gb>>>(
        P, fv_w2, nullptr, nullptr, P8, DD, DD, DD, 0, 0, 0, 1, 0, 0,
        (int64_t)NM * DD, fv_b1, 8, (int64_t)NM * DD);
    reduce_k<F_BIAS | F_ADD, 4><<<256, 256>>>(
        (const float2*)P8, fv_b2, (const float2*)h, (float2*)x2, MN2, NC2);
    // 7) A/B for edges (scalar, K-split 2 + reduce)
    float* P9 = P8 + 4 * NM * DD;
    gemm_k<0, 2><<<dim3(1, 16, 4), gb>>>(
        x2, fe_w1, nullptr, nullptr, P9, DD, DD, DD,
        0, (int64_t)DD * DD, 0, 1, (int64_t)NM * DD, 0, (int64_t)2 * NM * DD,
        nullptr, 1, 0);
    reduce_k<0, 2><<<512, 256>>>(
        (const float2*)P9, nullptr, nullptr, (float2*)ABuf, 2 * MN2, NC2);
    // 8) edge (packed f32x2)
    edge_k<<<dim3(16, 16, NB), 256>>>(ABuf, fe_b1, fe_w2, fe_b2, edge);
}

// round 17
// speedup vs baseline: 1.0780x; 1.0273x over previous
#include <cuda_runtime.h>
#include <cuda_bf16.h>
#include <math.h>
#include <stdint.h>

#define NB 2
#define MM 512
#define DD 128
#define HH 8
#define DIN 64
#define NM (NB*MM)   // 1024

typedef unsigned long long u64;

// ================= packed f32x2 helpers ===========================================
__device__ __forceinline__ u64 pk2(float lo, float hi) {
    u64 r; asm("mov.b64 %0, {%1,%2};" : "=l"(r) : "f"(lo), "f"(hi)); return r;
}
__device__ __forceinline__ void fma2(u64& d, u64 a, u64 b) {
    asm("fma.rn.f32x2 %0, %1, %2, %0;" : "+l"(d) : "l"(a), "l"(b));
}
__device__ __forceinline__ u64 add2(u64 a, u64 b) {
    u64 r; asm("add.rn.f32x2 %0, %1, %2;" : "=l"(r) : "l"(a), "l"(b)); return r;
}
__device__ __forceinline__ float2 up2(u64 v) {
    float lo, hi; asm("mov.b64 {%0,%1}, %2;" : "=f"(lo), "=f"(hi) : "l"(v));
    return make_float2(lo, hi);
}

// ================= mma.sync / cp.async helpers =====================================
__device__ __forceinline__ uint32_t smem_to_u32(const void* p) {
    uint32_t a;
    asm("{ .reg .u64 t; cvta.to.shared.u64 t, %1; cvt.u32.u64 %0, t; }" : "=r"(a) : "l"(p));
    return a;
}
__device__ __forceinline__ void ldsm4(uint32_t& r0, uint32_t& r1, uint32_t& r2,
                                      uint32_t& r3, uint32_t addr) {
    asm volatile("ldmatrix.sync.aligned.m8n8.x4.shared.b16 {%0,%1,%2,%3}, [%4];"
                 : "=r"(r0), "=r"(r1), "=r"(r2), "=r"(r3) : "r"(addr));
}
__device__ __forceinline__ void mma16816(float* d, uint32_t a0, uint32_t a1,
                                         uint32_t a2, uint32_t a3,
                                         uint32_t b0, uint32_t b1) {
    asm volatile("mma.sync.aligned.m16n8k16.row.col.f32.bf16.bf16.f32 "
                 "{%0,%1,%2,%3},{%4,%5,%6,%7},{%8,%9},{%0,%1,%2,%3};"
                 : "+f"(d[0]), "+f"(d[1]), "+f"(d[2]), "+f"(d[3])
                 : "r"(a0), "r"(a1), "r"(a2), "r"(a3), "r"(b0), "r"(b1));
}
__device__ __forceinline__ void cp16(uint32_t s, const void* g) {
    asm volatile("cp.async.cg.shared.global [%0], [%1], 16;" :: "r"(s), "l"(g));
}
#define CP_COMMIT() asm volatile("cp.async.commit_group;" ::: "memory")
#define CP_WAIT0()  asm volatile("cp.async.wait_group 0;" ::: "memory")

#define KT 32
#define SPAD 40

// C[64,128] += A[64,K] @ B[128,K]^T. 256 thr, 8 warps (2x4). cp.async 2-stage.
__device__ __forceinline__ void mma_loop64(
    const __nv_bfloat16* __restrict__ A, int lda,
    const __nv_bfloat16* __restrict__ B, int ldb,
    int nkt, float acc[2][4][4])
{
    __shared__ __nv_bfloat16 As[2][64][SPAD];
    __shared__ __nv_bfloat16 Bs[2][128][SPAD];
    int tid = threadIdx.x, lane = tid & 31, wid = tid >> 5;
    int wm = wid >> 2, wn = wid & 3;

    int arow_l = tid >> 2, acol_l = (tid & 3) << 3;
    int lrow = tid >> 1, lcol = (tid & 1) << 4;
    const __nv_bfloat16* Ag = A + (int64_t)arow_l * lda + acol_l;
    const __nv_bfloat16* Bg = B + (int64_t)lrow * ldb + lcol;

    uint32_t asb = smem_to_u32(As), bsb = smem_to_u32(Bs);
    int arow = ((lane >> 3) & 1) * 8 + (lane & 7);
    int acol = ((lane >> 4) & 1) * 8;
    int brow = ((lane >> 4) & 1) * 8 + (lane & 7);
    int bcol = ((lane >> 3) & 1) * 8;

    uint32_t adst = asb + (arow_l * SPAD + acol_l) * 2;
    uint32_t bdst = bsb + (lrow * SPAD + lcol) * 2;
    const uint32_t ABUF = 64 * SPAD * 2;
    const uint32_t BBUF = 128 * SPAD * 2;

    auto issue = [&](int kt, int bf) {
        cp16(adst + bf * ABUF,      Ag + kt * KT);
        cp16(bdst + bf * BBUF,      Bg + kt * KT);
        cp16(bdst + bf * BBUF + 16, Bg + kt * KT + 8);
        CP_COMMIT();
    };

    issue(0, 0);
    int buf = 0;
    for (int kt = 0; kt < nkt; kt++) {
        CP_WAIT0();
        __syncthreads();
        if (kt + 1 < nkt) issue(kt + 1, buf ^ 1);
        #pragma unroll
        for (int kf = 0; kf < 2; kf++) {
            uint32_t a[2][4];
            #pragma unroll
            for (int mf = 0; mf < 2; mf++)
                ldsm4(a[mf][0], a[mf][1], a[mf][2], a[mf][3],
                      asb + buf * ABUF + ((wm * 32 + mf * 16 + arow) * SPAD + kf * 16 + acol) * 2);
            uint32_t b[2][4];
            #pragma unroll
            for (int p = 0; p < 2; p++)
                ldsm4(b[p][0], b[p][1], b[p][2], b[p][3],
                      bsb + buf * BBUF + ((wn * 32 + p * 16 + brow) * SPAD + kf * 16 + bcol) * 2);
            #pragma unroll
            for (int mf = 0; mf < 2; mf++)
                #pragma unroll
                for (int nf = 0; nf < 4; nf++)
                    mma16816(acc[mf][nf], a[mf][0], a[mf][1], a[mf][2], a[mf][3],
                             b[nf >> 1][(nf & 1) * 2], b[nf >> 1][(nf & 1) * 2 + 1]);
        }
        buf ^= 1;
    }
}

// ================= scratch =========================================================
#define OFF_TMP   0
#define OFF_H     (OFF_TMP + NM*2*DD)
#define OFF_S     (OFF_H   + NM*DD)              // K-split partials region
#define OFF_ATTC  (OFF_S   + HH*NB*MM*MM)
#define OFF_T2    (OFF_ATTC+ HH*NM*DD)
#define OFF_AB    (OFF_T2  + NM*DD)
#define OFF_HB    (OFF_AB  + 2*NM*DD)
#define OFF_WTB   (OFF_HB  + NM*DD/2)
#define OFF_KB    (OFF_WTB + 3*HH*DD*DD/2)
#define OFF_QB    (OFF_KB  + HH*NM*DD/2)
#define OFF_VTB   (OFF_QB  + HH*NM*DD/2)
#define OFF_ALB   (OFF_VTB + HH*NM*DD/2)
#define OFF_FVWT  (OFF_ALB + HH*NB*MM*MM/2)
#define SCRATCH_TOTAL (OFF_FVWT + NM*DD/8)

__device__ float g_scratch[SCRATCH_TOTAL];

#define F_TRANSB 1
#define F_RELU   2
#define F_LEAKY  4
#define F_TE     8
#define F_BIAS   16
#define F_ADD    32
#define F_AR     64    // A = relu(sum_{r<nra} A[r*strideAR] + abias[kcol])
#define F_AH     128   // A = sum_{r<nra} A[r*strideAR] + abias[kcol] + hadd[row,kcol]; opt write x2out

// ================= scalar FFMA2 GEMM ===============================================
template<int F>
__device__ __forceinline__ void gemm_body(
    const float* __restrict__ A, const float* __restrict__ B,
    const float* __restrict__ bias, const float* __restrict__ addsrc,
    float* __restrict__ C, int Kd, int Nc, int ldc, int ktb, int kte,
    const float* __restrict__ abias, int nra, int64_t strideAR,
    const float* __restrict__ hadd, float* __restrict__ x2out)
{
    __shared__ float As[2][16][128];
    __shared__ float Bs[2][16][128];
    int tid = threadIdx.x;
    int tx = tid & 15, ty = tid >> 4;
    int m0 = blockIdx.y << 6, n0 = blockIdx.x << 7;

    int ar = tid >> 1, ac = (tid & 1) << 3;
    const float* Ap = A + (int64_t)(m0 + ar) * Kd + ac;
    int bk = tid >> 3, bc = (tid & 7) << 4;
    const float* Bp = (F & F_TRANSB)
        ? B + (int64_t)(n0 + tid) * Kd
        : B + (int64_t)bk * Nc + n0 + bc;

    u64 acc[8][4];
    #pragma unroll
    for (int i = 0; i < 8; i++)
        #pragma unroll
        for (int p = 0; p < 4; p++) acc[i][p] = 0ull;

    float4 la0, la1, lb[4];
    auto loadG = [&](int kt) {
        la0 = *(const float4*)(Ap + kt * 16);
        la1 = *(const float4*)(Ap + kt * 16 + 4);
        if (F & (F_AR | F_AH)) {
            for (int r = 1; r < nra; r++) {
                float4 u0 = *(const float4*)(Ap + r * strideAR + kt * 16);
                float4 u1 = *(const float4*)(Ap + r * strideAR + kt * 16 + 4);
                la0.x += u0.x; la0.y += u0.y; la0.z += u0.z; la0.w += u0.w;
                la1.x += u1.x; la1.y += u1.y; la1.z += u1.z; la1.w += u1.w;
            }
            float4 b0 = *(const float4*)(abias + kt * 16 + ac);
            float4 b1 = *(const float4*)(abias + kt * 16 + ac + 4);
            if (F & F_AR) {
                la0.x = fmaxf(la0.x + b0.x, 0.f); la0.y = fmaxf(la0.y + b0.y, 0.f);
                la0.z = fmaxf(la0.z + b0.z, 0.f); la0.w = fmaxf(la0.w + b0.w, 0.f);
                la1.x = fmaxf(la1.x + b1.x, 0.f); la1.y = fmaxf(la1.y + b1.y, 0.f);
                la1.z = fmaxf(la1.z + b1.z, 0.f); la1.w = fmaxf(la1.w + b1.w, 0.f);
            } else {
                const float* hrow = hadd + (int64_t)(m0 + ar) * Kd + kt * 16 + ac;
                float4 h0 = *(const float4*)(hrow);
                float4 h1 = *(const float4*)(hrow + 4);
                la0.x += b0.x + h0.x; la0.y += b0.y + h0.y;
                la0.z += b0.z + h0.z; la0.w += b0.w + h0.w;
                la1.x += b1.x + h1.x; la1.y += b1.y + h1.y;
                la1.z += b1.z + h1.z; la1.w += b1.w + h1.w;
                if (x2out) {
                    float* xrow = x2out + (int64_t)(m0 + ar) * Kd + kt * 16 + ac;
                    *(float4*)(xrow)     = la0;
                    *(float4*)(xrow + 4) = la1;
                }
            }
        }
        if (F & F_TE) {
            int kb = kt * 16 + ac;
            la0.x += sinf((float)(kb + 0) * (5.0f / 63.0f));
            la0.y += sinf((float)(kb + 1) * (5.0f / 63.0f));
            la0.z += sinf((float)(kb + 2) * (5.0f / 63.0f));
            la0.w += sinf((float)(kb + 3) * (5.0f / 63.0f));
            la1.x += sinf((float)(kb + 4) * (5.0f / 63.0f));
            la1.y += sinf((float)(kb + 5) * (5.0f / 63.0f));
            la1.z += sinf((float)(kb + 6) * (5.0f / 63.0f));
            la1.w += sinf((float)(kb + 7) * (5.0f / 63.0f));
        }
        if (F & F_TRANSB) {
            #pragma unroll
            for (int u = 0; u < 4; u++) lb[u] = *(const float4*)(Bp + kt * 16 + 4 * u);
        } else {
            #pragma unroll
            for (int u = 0; u < 4; u++) lb[u] = *(const float4*)(Bp + (int64_t)(kt * 16) * Nc + 4 * u);
        }
    };
    auto storeS = [&](int bf) {
        *(u64*)&As[bf][ac + 0][2 * ar] = pk2(la0.x, la0.x);
        *(u64*)&As[bf][ac + 1][2 * ar] = pk2(la0.y, la0.y);
        *(u64*)&As[bf][ac + 2][2 * ar] = pk2(la0.z, la0.z);
        *(u64*)&As[bf][ac + 3][2 * ar] = pk2(la0.w, la0.w);
        *(u64*)&As[bf][ac + 4][2 * ar] = pk2(la1.x, la1.x);
        *(u64*)&As[bf][ac + 5][2 * ar] = pk2(la1.y, la1.y);
        *(u64*)&As[bf][ac + 6][2 * ar] = pk2(la1.z, la1.z);
        *(u64*)&As[bf][ac + 7][2 * ar] = pk2(la1.w, la1.w);
        if (F & F_TRANSB) {
            #pragma unroll
            for (int u = 0; u < 4; u++) {
                Bs[bf][4 * u + 0][tid] = lb[u].x; Bs[bf][4 * u + 1][tid] = lb[u].y;
                Bs[bf][4 * u + 2][tid] = lb[u].z; Bs[bf][4 * u + 3][tid] = lb[u].w;
            }
        } else {
            #pragma unroll
            for (int u = 0; u < 4; u++) *(float4*)&Bs[bf][bk][bc + 4 * u] = lb[u];
        }
    };

    loadG(ktb); storeS(0); __syncthreads();
    int buf = 0;
    for (int kt = ktb; kt < kte; kt++) {
        bool more = (kt + 1 < kte);
        if (more) loadG(kt + 1);
        #pragma unroll
        for (int kk = 0; kk < 16; kk++) {
            ulonglong2 aL0 = *(const ulonglong2*)&As[buf][kk][(ty << 3)];
            ulonglong2 aL1 = *(const ulonglong2*)&As[buf][kk][(ty << 3) + 4];
            ulonglong2 aH0 = *(const ulonglong2*)&As[buf][kk][64 + (ty << 3)];
            ulonglong2 aH1 = *(const ulonglong2*)&As[buf][kk][64 + (ty << 3) + 4];
            ulonglong2 b0  = *(const ulonglong2*)&Bs[buf][kk][(tx << 2)];
            ulonglong2 b1  = *(const ulonglong2*)&Bs[buf][kk][64 + (tx << 2)];
            u64 ad[8] = {aL0.x, aL0.y, aL1.x, aL1.y, aH0.x, aH0.y, aH1.x, aH1.y};
            u64 bd[4] = {b0.x, b0.y, b1.x, b1.y};
            #pragma unroll
            for (int i = 0; i < 8; i++) {
                fma2(acc[i][0], ad[i], bd[0]);
                fma2(acc[i][1], ad[i], bd[1]);
                fma2(acc[i][2], ad[i], bd[2]);
                fma2(acc[i][3], ad[i], bd[3]);
            }
        }
        if (more) { storeS(buf ^ 1); __syncthreads(); buf ^= 1; }
    }

    #pragma unroll
    for (int i = 0; i < 8; i++) {
        int row = m0 + ((i < 4) ? ((ty << 2) + i) : (32 + (ty << 2) + i - 4));
        float2 q0 = up2(acc[i][0]), q1 = up2(acc[i][1]);
        float2 q2 = up2(acc[i][2]), q3 = up2(acc[i][3]);
        float o[8] = {q0.x, q0.y, q1.x, q1.y, q2.x, q2.y, q3.x, q3.y};
        #pragma unroll
        for (int j = 0; j < 8; j++) {
            int col = n0 + ((j < 4) ? ((tx << 2) + j) : (64 + (tx << 2) + j - 4));
            float v = o[j];
            if (F & F_BIAS)  v += bias[col];
            if (F & F_RELU)  v = fmaxf(v, 0.0f);
            if (F & F_LEAKY) v = (v >= 0.0f) ? v : 0.2f * v;
            if (F & F_ADD)   v += addsrc[(int64_t)row * ldc + col];
            o[j] = v;
        }
        *(float4*)&C[(int64_t)row * ldc + n0 + (tx << 2)]      = make_float4(o[0], o[1], o[2], o[3]);
        *(float4*)&C[(int64_t)row * ldc + n0 + 64 + (tx << 2)] = make_float4(o[4], o[5], o[6], o[7]);
    }
}

template<int F, int NKS>
__global__ __launch_bounds__(128, 4)
void gemm_k(const float* __restrict__ A, const float* __restrict__ B,
            const float* __restrict__ bias, const float* __restrict__ addsrc,
            float* __restrict__ C, int Kd, int Nc, int ldc,
            int64_t sA, int64_t sB, int64_t sBias,
            int zdiv, int64_t sC1, int64_t sC2, int64_t sPart,
            const float* abias, int nra, int64_t strideAR,
            const float* hadd, float* x2out)
{
    int zz = blockIdx.z;
    int z = zz / NKS, ks = zz % NKS;
    int ktn = Kd >> 4;
    int ktb = ks * (ktn / NKS), kte = ktb + ktn / NKS;
    const float* bz = (F & F_BIAS) ? bias + sBias * z : nullptr;
    float* Cz = C + (int64_t)(z / zdiv) * sC1 + (int64_t)(z % zdiv) * sC2
                  + (int64_t)ks * sPart;
    float* xo = ((F & F_AH) && z == 0) ? x2out : nullptr;
    gemm_body<F>(A + sA * z, B + sB * z, bz, addsrc, Cz, Kd, Nc, ldc, ktb, kte,
                 abias, nra, strideAR, hadd, xo);
}

// ================= float2-granularity K-split reduce ===============================
template<int F, int NKS>
__global__ __launch_bounds__(256)
void reduce_k(const float2* __restrict__ P, const float* __restrict__ bias,
              const float2* __restrict__ addsrc, float2* __restrict__ C,
              int totalf2, int ncf2)
{
    int idx = blockIdx.x * 256 + threadIdx.x;
    if (idx >= totalf2) return;
    float2 s = P[idx];
    #pragma unroll
    for (int k = 1; k < NKS; k++) {
        float2 t = P[idx + (int64_t)k * totalf2];
        s.x += t.x; s.y += t.y;
    }
    if (F & F_BIAS) {
        float2 b = ((const float2*)bias)[idx % ncf2];
        s.x += b.x; s.y += b.y;
    }
    if (F & F_RELU) { s.x = fmaxf(s.x, 0.f); s.y = fmaxf(s.y, 0.f); }
    if (F & F_ADD)  { float2 a = addsrc[idx]; s.x += a.x; s.y += a.y; }
    C[idx] = s;
}

// ================= fused prep ======================================================
__global__ __launch_bounds__(256)
void fuse_prep_k(const float2* __restrict__ Ph, const float* __restrict__ fn_b2,
                 float2* __restrict__ h, __nv_bfloat16* __restrict__ hb,
                 const float* __restrict__ wk, const float* __restrict__ wq,
                 const float* __restrict__ wv, const float* __restrict__ fv_w1,
                 __nv_bfloat16* __restrict__ wtb, __nv_bfloat16* __restrict__ fvwt)
{
    int b = blockIdx.x, t = threadIdx.x;
    if (b < 256) {
        int idx = b * 256 + t;
        float2 s = Ph[idx];
        #pragma unroll
        for (int k = 1; k < 8; k++) {
            float2 v = Ph[idx + k * (NM * DD / 2)];
            s.x += v.x; s.y += v.y;
        }
        float2 bb = ((const float2*)fn_b2)[idx & 63];
        s.x += bb.x; s.y += bb.y;
        h[idx] = s;
        __nv_bfloat162 p = __floats2bfloat162_rn(s.x, s.y);
        *(uint32_t*)&hb[idx * 2] = *(uint32_t*)&p;
        return;
    }
    __shared__ float ts[32][33];
    int c = t & 31, r0 = t >> 5;
    if (b < 640) {
        int q = b - 256;
        int mi = q >> 4, ti = q & 15;
        int kb = ti >> 2, nb = ti & 3;
        int w = mi / 8, hd = mi & 7;
        const float* src = ((w == 0) ? wk : (w == 1) ? wq : wv) + hd * 16384;
        #pragma unroll
        for (int i = 0; i < 4; i++) {
            int r = r0 + 8 * i;
            ts[r][c] = src[(kb * 32 + r) * 128 + nb * 32 + c];
        }
        __syncthreads();
        int ck = (t & 15) << 1, rn0 = t >> 4;
        __nv_bfloat16* dst = wtb + (int64_t)mi * 16384;
        #pragma unroll
        for (int i = 0; i < 2; i++) {
            int rn = rn0 + 16 * i;
            __nv_bfloat162 p = __floats2bfloat162_rn(ts[ck][rn], ts[ck + 1][rn]);
            *(uint32_t*)&dst[(nb * 32 + rn) * 128 + kb * 32 + ck] = *(uint32_t*)&p;
        }
    } else {
        int q = b - 640;
        int kb = q >> 2, nb = q & 3;
        #pragma unroll
        for (int i = 0; i < 4; i++) {
            int r = r0 + 8 * i;
            ts[r][c] = fv_w1[(kb * 32 + r) * 128 + nb * 32 + c];
        }
        __syncthreads();
        int ck = (t & 15) << 1, rn0 = t >> 4;
        #pragma unroll
        for (int i = 0; i < 2; i++) {
            int rn = rn0 + 16 * i;
            __nv_bfloat162 p = __floats2bfloat162_rn(ts[ck][rn], ts[ck + 1][rn]);
            *(uint32_t*)&fvwt[(int64_t)(nb * 32 + rn) * 1024 + kb * 32 + ck] = *(uint32_t*)&p;
        }
    }
}

// ================= KQV via mma.sync, M-tile 64 =====================================
__global__ __launch_bounds__(256)
void kqv_mma_k(const __nv_bfloat16* __restrict__ hb, const __nv_bfloat16* __restrict__ wtb,
               const float* __restrict__ bk, const float* __restrict__ bq,
               const float* __restrict__ bv,
               __nv_bfloat16* __restrict__ Kb, __nv_bfloat16* __restrict__ Qb,
               __nv_bfloat16* __restrict__ Vtb)
{
    __shared__ __nv_bfloat16 Vs[128][72];
    int z = blockIdx.z, which = z >> 3, head = z & 7;
    int m0 = blockIdx.y << 6;
    float acc[2][4][4] = {};
    mma_loop64(hb + (int64_t)m0 * DD, DD,
               wtb + (int64_t)z * DD * DD, DD, DD / KT, acc);

    int tid = threadIdx.x;
    int lane = tid & 31, wid = tid >> 5;
    int wm = wid >> 2, wn = wid & 3;
    const float* bias = ((which == 0) ? bk : (which == 1) ? bq : bv) + head * DD;

    if (which < 2) {
        __nv_bfloat16* out = ((which == 0) ? Kb : Qb) + (int64_t)head * NM * DD;
        #pragma unroll
        for (int mf = 0; mf < 2; mf++) {
            #pragma unroll
            for (int nf = 0; nf < 4; nf++) {
                int r   = wm * 32 + mf * 16 + (lane >> 2);
                int col = wn * 32 + nf * 8 + ((lane & 3) << 1);
                float b0 = bias[col], b1 = bias[col + 1];
                __nv_bfloat162 p0 = __floats2bfloat162_rn(acc[mf][nf][0] + b0, acc[mf][nf][1] + b1);
                __nv_bfloat162 p1 = __floats2bfloat162_rn(acc[mf][nf][2] + b0, acc[mf][nf][3] + b1);
                *(uint32_t*)&out[(int64_t)(m0 + r) * DD + col]     = *(uint32_t*)&p0;
                *(uint32_t*)&out[(int64_t)(m0 + r + 8) * DD + col] = *(uint32_t*)&p1;
            }
        }
    } else {
        __syncthreads();
        #pragma unroll
        for (int mf = 0; mf < 2; mf++) {
            #pragma unroll
            for (int nf = 0; nf < 4; nf++) {
                int r   = wm * 32 + mf * 16 + (lane >> 2);
                int col = wn * 32 + nf * 8 + ((lane & 3) << 1);
                float b0 = bias[col], b1 = bias[col + 1];
                Vs[col][r]         = __float2bfloat16(acc[mf][nf][0] + b0);
                Vs[col + 1][r]     = __float2bfloat16(acc[mf][nf][1] + b1);
                Vs[col][r + 8]     = __float2bfloat16(acc[mf][nf][2] + b0);
                Vs[col + 1][r + 8] = __float2bfloat16(acc[mf][nf][3] + b1);
            }
        }
        __syncthreads();
        int d = tid >> 1, half = tid & 1;
        int n = m0 >> 9;
        __nv_bfloat16* vt = Vtb + ((int64_t)(head * 2 + n) * DD + d) * MM
                            + (m0 & 511) + half * 32;
        #pragma unroll
        for (int q = 0; q < 4; q++)
            *(uint4*)(vt + 8 * q) = *(const uint4*)&Vs[d][half * 32 + 8 * q];
    }
}

// ================= MEGA: scores+softmax+attV+fv1 in one kernel =====================
#define AM_SMEM 158720
#define ALP 520
#define ATTP 136
__global__ __launch_bounds__(256)
void attn_mega_k(const __nv_bfloat16* __restrict__ Kb,
                 const __nv_bfloat16* __restrict__ Qb,
                 const __nv_bfloat16* __restrict__ Vtb,
                 const __nv_bfloat16* __restrict__ fvwt,
                 float* __restrict__ P)
{
    extern __shared__ char dsm[];
    int tid = threadIdx.x, lane = tid & 31, wid = tid >> 5;
    int wm = wid >> 2, wn = wid & 3;
    int z = blockIdx.z, h = z >> 1, n = z & 1;
    int m0 = blockIdx.y << 6;

    uint32_t base = smem_to_u32(dsm);
    uint32_t alp  = base + 92160;

    int arow = ((lane >> 3) & 1) * 8 + (lane & 7);
    int acol = ((lane >> 4) & 1) * 8;
    int brow = ((lane >> 4) & 1) * 8 + (lane & 7);
    int bcol = ((lane >> 3) & 1) * 8;
    int r4 = lane >> 2, q = lane & 3;

    // ---------- stage A: scores = K @ Q^T ----------
    {
        uint32_t asb = base, bsb = base + 2 * 64 * SPAD * 2;
        const uint32_t ABUF = 64 * SPAD * 2, BBUF = 512 * SPAD * 2;
        const __nv_bfloat16* Ag = Kb + ((int64_t)h * NM + n * MM + m0) * DD;
        const __nv_bfloat16* Bg = Qb + ((int64_t)h * NM + n * MM) * DD;
        int ar_l = tid >> 2, ach = (tid & 3) << 3;
        auto issue = [&](int kt, int bf) {
            cp16(asb + bf * ABUF + (ar_l * SPAD + ach) * 2,
                 Ag + (int64_t)ar_l * DD + kt * KT + ach);
            #pragma unroll
            for (int i = 0; i < 8; i++) {
                int id = tid + 256 * i;
                int br_l = id >> 2, bch = (id & 3) << 3;
                cp16(bsb + bf * BBUF + (br_l * SPAD + bch) * 2,
                     Bg + (int64_t)br_l * DD + kt * KT + bch);
            }
            CP_COMMIT();
        };

        float acc[4][8][4];
        #pragma unroll
        for (int mf = 0; mf < 4; mf++)
            #pragma unroll
            for (int nf = 0; nf < 8; nf++)
                #pragma unroll
                for (int i = 0; i < 4; i++) acc[mf][nf][i] = 0.f;

        issue(0, 0);
        int buf = 0;
        for (int kt = 0; kt < 4; kt++) {
            CP_WAIT0();
            __syncthreads();
            if (kt + 1 < 4) issue(kt + 1, buf ^ 1);
            #pragma unroll
            for (int kf = 0; kf < 2; kf++) {
                uint32_t a[4][4];
                #pragma unroll
                for (int mf = 0; mf < 4; mf++)
                    ldsm4(a[mf][0], a[mf][1], a[mf][2], a[mf][3],
                          asb + buf * ABUF + ((mf * 16 + arow) * SPAD + kf * 16 + acol) * 2);
                uint32_t b[4][4];
                #pragma unroll
                for (int p = 0; p < 4; p++)
                    ldsm4(b[p][0], b[p][1], b[p][2], b[p][3],
                          bsb + buf * BBUF + ((wid * 64 + p * 16 + brow) * SPAD + kf * 16 + bcol) * 2);
                #pragma unroll
                for (int mf = 0; mf < 4; mf++)
                    #pragma unroll
                    for (int p = 0; p < 4; p++) {
                        mma16816(acc[mf][p * 2],     a[mf][0], a[mf][1], a[mf][2], a[mf][3],
                                 b[p][0], b[p][1]);
                        mma16816(acc[mf][p * 2 + 1], a[mf][0], a[mf][1], a[mf][2], a[mf][3],
                                 b[p][2], b[p][3]);
                    }
            }
            buf ^= 1;
        }
        __syncthreads();

        // ---------- stage B: softmax -> alpha in smem ----------
        float* pmax = (float*)dsm;
        float* psum = pmax + 512;

        #pragma unroll
        for (int mf = 0; mf < 4; mf++) {
            float m0v = -1e30f, m1v = -1e30f;
            #pragma unroll
            for (int nf = 0; nf < 8; nf++) {
                #pragma unroll
                for (int i = 0; i < 4; i++) {
                    float v = acc[mf][nf][i];
                    v = (v >= 0.f) ? v : 0.2f * v;
                    acc[mf][nf][i] = v;
                }
                m0v = fmaxf(m0v, fmaxf(acc[mf][nf][0], acc[mf][nf][1]));
                m1v = fmaxf(m1v, fmaxf(acc[mf][nf][2], acc[mf][nf][3]));
            }
            m0v = fmaxf(m0v, __shfl_xor_sync(0xffffffffu, m0v, 1));
            m0v = fmaxf(m0v, __shfl_xor_sync(0xffffffffu, m0v, 2));
            m1v = fmaxf(m1v, __shfl_xor_sync(0xffffffffu, m1v, 1));
            m1v = fmaxf(m1v, __shfl_xor_sync(0xffffffffu, m1v, 2));
            if (q == 0) {
                pmax[(mf * 16 + r4) * 8 + wid]     = m0v;
                pmax[(mf * 16 + 8 + r4) * 8 + wid] = m1v;
            }
        }
        __syncthreads();
        float gmx[4][2];
        #pragma unroll
        for (int mf = 0; mf < 4; mf++) {
            float g0 = pmax[(mf * 16 + r4) * 8];
            float g1 = pmax[(mf * 16 + 8 + r4) * 8];
            #pragma unroll
            for (int w = 1; w < 8; w++) {
                g0 = fmaxf(g0, pmax[(mf * 16 + r4) * 8 + w]);
                g1 = fmaxf(g1, pmax[(mf * 16 + 8 + r4) * 8 + w]);
            }
            gmx[mf][0] = g0; gmx[mf][1] = g1;
        }
        #pragma unroll
        for (int mf = 0; mf < 4; mf++) {
            float s0 = 0.f, s1 = 0.f;
            #pragma unroll
            for (int nf = 0; nf < 8; nf++) {
                float e0 = __expf(acc[mf][nf][0] - gmx[mf][0]);
                float e1 = __expf(acc[mf][nf][1] - gmx[mf][0]);
                float e2 = __expf(acc[mf][nf][2] - gmx[mf][1]);
                float e3 = __expf(acc[mf][nf][3] - gmx[mf][1]);
                acc[mf][nf][0] = e0; acc[mf][nf][1] = e1;
                acc[mf][nf][2] = e2; acc[mf][nf][3] = e3;
                s0 += e0 + e1; s1 += e2 + e3;
            }
            s0 += __shfl_xor_sync(0xffffffffu, s0, 1);
            s0 += __shfl_xor_sync(0xffffffffu, s0, 2);
            s1 += __shfl_xor_sync(0xffffffffu, s1, 1);
            s1 += __shfl_xor_sync(0xffffffffu, s1, 2);
            if (q == 0) {
                psum[(mf * 16 + r4) * 8 + wid]     = s0;
                psum[(mf * 16 + 8 + r4) * 8 + wid] = s1;
            }
        }
        __syncthreads();
        __nv_bfloat16* Alpha = (__nv_bfloat16*)(dsm + 92160);
        #pragma unroll
        for (int mf = 0; mf < 4; mf++) {
            float g0 = 0.f, g1 = 0.f;
            #pragma unroll
            for (int w = 0; w < 8; w++) {
                g0 += psum[(mf * 16 + r4) * 8 + w];
                g1 += psum[(mf * 16 + 8 + r4) * 8 + w];
            }
            float inv0 = 1.0f / g0, inv1 = 1.0f / g1;
            int row0 = mf * 16 + r4, row1 = row0 + 8;
            #pragma unroll
            for (int nf = 0; nf < 8; nf++) {
                int col = wid * 64 + nf * 8 + (q << 1);
                __nv_bfloat162 p0 = __floats2bfloat162_rn(acc[mf][nf][0] * inv0, acc[mf][nf][1] * inv0);
                __nv_bfloat162 p1 = __floats2bfloat162_rn(acc[mf][nf][2] * inv1, acc[mf][nf][3] * inv1);
                *(uint32_t*)&Alpha[row0 * ALP + col] = *(uint32_t*)&p0;
                *(uint32_t*)&Alpha[row1 * ALP + col] = *(uint32_t*)&p1;
            }
        }
        __syncthreads();
    }

    // ---------- stage C: att = alpha @ V^T ----------
    float accv[2][4][4] = {};
    {
        uint32_t bsb = base;
        const uint32_t BBUF = 128 * SPAD * 2;
        int lrow = tid >> 1, lcol = (tid & 1) << 4;
        const __nv_bfloat16* Bg = Vtb + (int64_t)z * DD * MM + (int64_t)lrow * MM + lcol;
        uint32_t bdst = bsb + (lrow * SPAD + lcol) * 2;

        auto issue = [&](int kt, int bf) {
            cp16(bdst + bf * BBUF,      Bg + kt * KT);
            cp16(bdst + bf * BBUF + 16, Bg + kt * KT + 8);
            CP_COMMIT();
        };

        issue(0, 0);
        int buf = 0;
        for (int kt = 0; kt < MM / KT; kt++) {
            CP_WAIT0();
            __syncthreads();
            if (kt + 1 < MM / KT) issue(kt + 1, buf ^ 1);
            #pragma unroll
            for (int kf = 0; kf < 2; kf++) {
                uint32_t a[2][4];
                #pragma unroll
                for (int mf = 0; mf < 2; mf++)
                    ldsm4(a[mf][0], a[mf][1], a[mf][2], a[mf][3],
                          alp + ((wm * 32 + mf * 16 + arow) * ALP + kt * KT + kf * 16 + acol) * 2);
                uint32_t b[2][4];
                #pragma unroll
                for (int p = 0; p < 2; p++)
                    ldsm4(b[p][0], b[p][1], b[p][2], b[p][3],
                          bsb + buf * BBUF + ((wn * 32 + p * 16 + brow) * SPAD + kf * 16 + bcol) * 2);
                #pragma unroll
                for (int mf = 0; mf < 2; mf++)
                    #pragma unroll
                    for (int nf = 0; nf < 4; nf++)
                        mma16816(accv[mf][nf], a[mf][0], a[mf][1], a[mf][2], a[mf][3],
                                 b[nf >> 1][(nf & 1) * 2], b[nf >> 1][(nf & 1) * 2 + 1]);
            }
            buf ^= 1;
        }
    }

    // leaky + bf16 into Att
    {
        __nv_bfloat16* Att = (__nv_bfloat16*)(dsm + 20480);
        #pragma unroll
        for (int mf = 0; mf < 2; mf++) {
            #pragma unroll
            for (int nf = 0; nf < 4; nf++) {
                int r   = wm * 32 + mf * 16 + (lane >> 2);
                int col = wn * 32 + nf * 8 + ((lane & 3) << 1);
                float v0 = accv[mf][nf][0]; v0 = (v0 >= 0.f) ? v0 : 0.2f * v0;
                float v1 = accv[mf][nf][1]; v1 = (v1 >= 0.f) ? v1 : 0.2f * v1;
                float v2 = accv[mf][nf][2]; v2 = (v2 >= 0.f) ? v2 : 0.2f * v2;
                float v3 = accv[mf][nf][3]; v3 = (v3 >= 0.f) ? v3 : 0.2f * v3;
                __nv_bfloat162 p0 = __floats2bfloat162_rn(v0, v1);
                __nv_bfloat162 p1 = __floats2bfloat162_rn(v2, v3);
                *(uint32_t*)&Att[r * ATTP + col]       = *(uint32_t*)&p0;
                *(uint32_t*)&Att[(r + 8) * ATTP + col] = *(uint32_t*)&p1;
            }
        }
    }

    // ---------- stage D: P[h] = Att @ fvwt[:, h*128..]^T ----------
    {
        uint32_t atb = base + 20480;
        uint32_t b2b = base + 37888;
        const uint32_t BBUF2 = 128 * SPAD * 2;
        int lrow = tid >> 1, lcol = (tid & 1) << 4;
        const __nv_bfloat16* Bg = fvwt + (int64_t)lrow * (HH * DD) + h * DD + lcol;
        uint32_t bdst = b2b + (lrow * SPAD + lcol) * 2;

        auto issue2 = [&](int kt, int bf) {
            cp16(bdst + bf * BBUF2,      Bg + kt * KT);
            cp16(bdst + bf * BBUF2 + 16, Bg + kt * KT + 8);
            CP_COMMIT();
        };

        float acc2[2][4][4] = {};
        issue2(0, 0);
        int buf = 0;
        for (int kt = 0; kt < 4; kt++) {
            CP_WAIT0();
            __syncthreads();
            if (kt + 1 < 4) issue2(kt + 1, buf ^ 1);
            #pragma unroll
            for (int kf = 0; kf < 2; kf++) {
                uint32_t a[2][4];
                #pragma unroll
                for (int mf = 0; mf < 2; mf++)
                    ldsm4(a[mf][0], a[mf][1], a[mf][2], a[mf][3],
                          atb + ((wm * 32 + mf * 16 + arow) * ATTP + kt * KT + kf * 16 + acol) * 2);
                uint32_t b[2][4];
                #pragma unroll
                for (int p = 0; p < 2; p++)
                    ldsm4(b[p][0], b[p][1], b[p][2], b[p][3],
                          b2b + buf * BBUF2 + ((wn * 32 + p * 16 + brow) * SPAD + kf * 16 + bcol) * 2);
                #pragma unroll
                for (int mf = 0; mf < 2; mf++)
                    #pragma unroll
                    for (int nf = 0; nf < 4; nf++)
                        mma16816(acc2[mf][nf], a[mf][0], a[mf][1], a[mf][2], a[mf][3],
                                 b[nf >> 1][(nf & 1) * 2], b[nf >> 1][(nf & 1) * 2 + 1]);
            }
            buf ^= 1;
        }

        float* out = P + (int64_t)h * NM * DD;
        #pragma unroll
        for (int mf = 0; mf < 2; mf++) {
            #pragma unroll
            for (int nf = 0; nf < 4; nf++) {
                int r   = n * MM + m0 + wm * 32 + mf * 16 + (lane >> 2);
                int col = wn * 32 + nf * 8 + ((lane & 3) << 1);
                *(float2*)&out[(int64_t)r * DD + col]       = make_float2(acc2[mf][nf][0], acc2[mf][nf][1]);
                *(float2*)&out[(int64_t)(r + 8) * DD + col] = make_float2(acc2[mf][nf][2], acc2[mf][nf][3]);
            }
        }
    }
}

// ================= edge kernel: packed f32x2 + abs-trick ===========================
__global__ __launch_bounds__(256)
void edge_k(const float* __restrict__ AB, const float* __restrict__ b1,
            const float* __restrict__ w2, const float* __restrict__ b2,
            float* __restrict__ out)
{
    __shared__ float Ast[DD][68];
    __shared__ float Bst[DD][36];
    __shared__ u64 w2d[DD];
    int n  = blockIdx.z;
    int i0 = blockIdx.y << 5, j0 = blockIdx.x << 5;
    const float* Ab = AB + ((int64_t)n * MM + i0) * DD;
    const float* Bb = AB + (int64_t)NM * DD + ((int64_t)n * MM + j0) * DD;
    int t = threadIdx.x;
    if (t < DD) { float w = w2[t] * 0.5f; w2d[t] = pk2(w, w); }
    #pragma unroll
    for (int c = 0; c < 4; c++) {
        int idx = t + (c << 8);
        int r  = idx >> 5;
        int d4 = (idx & 31) << 2;
        float4 a = *(const float4*)(Ab + r * DD + d4);
        *(u64*)&Ast[d4 + 0][2 * r] = pk2(a.x, a.x);
        *(u64*)&Ast[d4 + 1][2 * r] = pk2(a.y, a.y);
        *(u64*)&Ast[d4 + 2][2 * r] = pk2(a.z, a.z);
        *(u64*)&Ast[d4 + 3][2 * r] = pk2(a.w, a.w);
        float4 bvl = *(const float4*)(Bb + r * DD + d4);
        float4 bb  = *(const float4*)(b1 + d4);
        Bst[d4 + 0][r] = bvl.x + bb.x; Bst[d4 + 1][r] = bvl.y + bb.y;
        Bst[d4 + 2][r] = bvl.z + bb.z; Bst[d4 + 3][r] = bvl.w + bb.w;
    }
    __syncthreads();
    int tx = t & 15, ty = t >> 4;
    const u64 MASK = 0x7FFFFFFF7FFFFFFFull;
    u64 acc0 = 0ull, acc1 = 0ull;
    #pragma unroll 4
    for (int d = 0; d < DD; d++) {
        u64 a0 = *(const u64*)&Ast[d][ty << 2];
        u64 a1 = *(const u64*)&Ast[d][(ty << 2) + 2];
        u64 bp = *(const u64*)&Bst[d][tx << 1];
        u64 wd = w2d[d];
        u64 s0 = add2(a0, bp);
        u64 s1 = add2(a1, bp);
        u64 t0 = s0 & MASK;
        u64 t1 = s1 & MASK;
        fma2(acc0, s0, wd); fma2(acc0, t0, wd);
        fma2(acc1, s1, wd); fma2(acc1, t1, wd);
    }
    float bb = b2[0];
    const float sc = 1.0f / (float)MM;
    int i = i0 + (ty << 1), j = j0 + (tx << 1);
    float2 q0 = up2(acc0), q1 = up2(acc1);
    float* o = out + ((int64_t)n * MM + i) * MM + j;
    *(float2*)o        = make_float2((q0.x + bb) * sc, (q0.y + bb) * sc);
    *(float2*)(o + MM) = make_float2((q1.x + bb) * sc, (q1.y + bb) * sc);
}

// ================= host launcher ===================================================
extern "C" void kernel_launch(void* const* d_in, const int* in_sizes, int n_in,
                              void* d_out, int out_size)
{
    const float* x     = (const float*)d_in[0];
    const float* fn_w1 = (const float*)d_in[1];
    const float* fn_b1 = (const float*)d_in[2];
    const float* fn_w2 = (const float*)d_in[3];
    const float* fn_b2 = (const float*)d_in[4];
    const float* wk    = (const float*)d_in[5];
    const float* bk    = (const float*)d_in[6];
    const float* wq    = (const float*)d_in[7];
    const float* bq    = (const float*)d_in[8];
    const float* wv    = (const float*)d_in[9];
    const float* bv    = (const float*)d_in[10];
    const float* fv_w1 = (const float*)d_in[11];
    const float* fv_b1 = (const float*)d_in[12];
    const float* fv_w2 = (const float*)d_in[13];
    const float* fv_b2 = (const float*)d_in[14];
    const float* fe_w1 = (const float*)d_in[15];
    const float* fe_b1 = (const float*)d_in[16];
    const float* fe_w2 = (const float*)d_in[17];
    const float* fe_b2 = (const float*)d_in[18];

    float* scratch = nullptr;
    cudaGetSymbolAddress((void**)&scratch, g_scratch);
    float* h    = scratch + OFF_H;
    float* P    = scratch + OFF_S;
    float* ABuf = scratch + OFF_AB;
    __nv_bfloat16* hb  = (__nv_bfloat16*)(scratch + OFF_HB);
    __nv_bfloat16* wtb = (__nv_bfloat16*)(scratch + OFF_WTB);
    __nv_bfloat16* Kb  = (__nv_bfloat16*)(scratch + OFF_KB);
    __nv_bfloat16* Qb  = (__nv_bfloat16*)(scratch + OFF_QB);
    __nv_bfloat16* Vtb = (__nv_bfloat16*)(scratch + OFF_VTB);
    __nv_bfloat16* fvwt = (__nv_bfloat16*)(scratch + OFF_FVWT);

    float* x2   = (float*)d_out;
    float* edge = (float*)d_out + NM * DD;

    cudaFuncSetAttribute(attn_mega_k,
                         cudaFuncAttributeMaxDynamicSharedMemorySize, AM_SMEM);

    dim3 gb(128);
    const int MN2 = NM * DD / 2;
    const int NC2 = DD / 2;

    // 1) f_node hidden (scalar, K-split 2) -> partials
    gemm_k<F_TE, 2><<<dim3(2, 16, 2), gb>>>(
        x, fn_w1, nullptr, nullptr, P, DIN, 2 * DD, 2 * DD, 0, 0, 0, 1, 0, 0,
        (int64_t)NM * 2 * DD, nullptr, 1, 0, nullptr, nullptr);
    // 2) h (scalar, K-split 8); A-loader reduces f_node1 partials
    float* Ph = P + NM * 2 * DD * 2;
    gemm_k<F_AR, 8><<<dim3(1, 16, 8), gb>>>(
        P, fn_w2, nullptr, nullptr, Ph, 2 * DD, DD, DD, 0, 0, 0, 1, 0, 0,
        (int64_t)NM * DD, fn_b1, 2, (int64_t)NM * 2 * DD, nullptr, nullptr);
    fuse_prep_k<<<768, 256>>>((const float2*)Ph, fn_b2, (float2*)h, hb,
                              wk, wq, wv, fv_w1, wtb, fvwt);
    // 3) K/Q/V via mma.sync, M-tile 64
    kqv_mma_k<<<dim3(1, 16, 24), 256>>>(hb, wtb, bk, bq, bv, Kb, Qb, Vtb);
    // 4) MEGA: scores+softmax+attV+fv1 (alpha never leaves smem) -> partials P[h]
    attn_mega_k<<<dim3(1, 8, 16), 256, AM_SMEM>>>(Kb, Qb, Vtb, fvwt, P);
    // 5) x2-partials (scalar, K-split 4); A-loader reduces fv1 partials
    float* P8 = P + 8 * NM * DD;
    gemm_k<F_AR, 4><<<dim3(1, 16, 4), gb>>>(
        P, fv_w2, nullptr, nullptr, P8, DD, DD, DD, 0, 0, 0, 1, 0, 0,
        (int64_t)NM * DD, fv_b1, 8, (int64_t)NM * DD, nullptr, nullptr);
    // 6) A/B for edges; A-loader reduces x2 partials (+fv_b2 +h) and writes x2 out
    float* P9 = P8 + 4 * NM * DD;
    gemm_k<F_AH, 2><<<dim3(1, 16, 4), gb>>>(
        P8, fe_w1, nullptr, nullptr, P9, DD, DD, DD,
        0, (int64_t)DD * DD, 0, 1, (int64_t)NM * DD, 0, (int64_t)2 * NM * DD,
        fv_b2, 4, (int64_t)NM * DD, h, x2);
    reduce_k<0, 2><<<512, 256>>>(
        (const float2*)P9, nullptr, nullptr, (float2*)ABuf, 2 * MN2, NC2);
    // 7) edge (packed f32x2)
    edge_k<<<dim3(16, 16, NB), 256>>>(ABuf, fe_b1, fe_w2, fe_b2, edge);
}